// round 1
// baseline (speedup 1.0000x reference)
#include <cuda_runtime.h>
#include <math.h>

// Problem constants (fixed by the reference setup)
#define B_    2
#define S_    2048
#define H_    2048
#define HEADS 16
#define DH    128          // H_/HEADS
#define BH    (B_*HEADS)   // 32
#define BSH   ((size_t)B_*S_*H_)   // 8,388,608

// ---------------------------------------------------------------------------
// Scratch (static device globals — no allocation in kernel_launch)
// ---------------------------------------------------------------------------
__device__ float g_qkv[(size_t)B_*S_*3*H_];            // [B,S,3H]   ~100.7 MB
__device__ float g_q[BSH];                             // [B,HEADS,S,DH] 33.5 MB
__device__ float g_scores[(size_t)BH*S_*S_];           // [BH,S,S]   ~537 MB
__device__ float g_ctxh[BSH];                          // [B,HEADS,S,DH]

// ---------------------------------------------------------------------------
// LayerNorm: one block per row of x [B*S, H]
// ---------------------------------------------------------------------------
__global__ void __launch_bounds__(256) ln_kernel(
    const float* __restrict__ x, const float* __restrict__ g,
    const float* __restrict__ b, float* __restrict__ y)
{
    const size_t row = blockIdx.x;
    const float* xr = x + row * H_;
    float s = 0.f, ss = 0.f;
    for (int i = threadIdx.x; i < H_; i += 256) {
        float t = xr[i];
        s += t; ss += t * t;
    }
    #pragma unroll
    for (int o = 16; o; o >>= 1) {
        s  += __shfl_xor_sync(0xffffffffu, s,  o);
        ss += __shfl_xor_sync(0xffffffffu, ss, o);
    }
    __shared__ float red[2][8];
    const int w = threadIdx.x >> 5, l = threadIdx.x & 31;
    if (l == 0) { red[0][w] = s; red[1][w] = ss; }
    __syncthreads();
    __shared__ float stats[2];
    if (threadIdx.x == 0) {
        float S = 0.f, SS = 0.f;
        #pragma unroll
        for (int i = 0; i < 8; i++) { S += red[0][i]; SS += red[1][i]; }
        float mu  = S / (float)H_;
        float var = SS / (float)H_ - mu * mu;
        stats[0] = mu;
        stats[1] = rsqrtf(var + 1e-12f);
    }
    __syncthreads();
    const float mu = stats[0], rstd = stats[1];
    float* yr = y + row * H_;
    for (int i = threadIdx.x; i < H_; i += 256)
        yr[i] = (xr[i] - mu) * rstd * g[i] + b[i];
}

// ---------------------------------------------------------------------------
// Tiled SGEMM: C[M,N] = A[M,K] * B (NN) or A[M,K] * B^T (NT, B is [N,K])
// Block tile 128x128, K-step 8, 256 threads, 8x8 per thread.
// Batched via blockIdx.z with element strides sA/sB/sC.
// EPI: 0 = plain, 1 = +bias[n], 2 = attention epilogue
//      (v = n<=m ? v*scale + mask[batch][n] : -10000)
// ---------------------------------------------------------------------------
template<bool TRANSB, int EPI>
__global__ void __launch_bounds__(256) sgemm(
    const float* __restrict__ A, const float* __restrict__ Bm,
    float* __restrict__ C, int M, int N, int K,
    size_t sA, size_t sB, size_t sC,
    const float* __restrict__ extra, float scale, int maskStride)
{
    const int bz = blockIdx.z;
    A  += (size_t)bz * sA;
    Bm += (size_t)bz * sB;
    C  += (size_t)bz * sC;

    __shared__ float As[8][128];
    __shared__ float Bs[8][128];

    const int tx = threadIdx.x;
    const int rowBase = blockIdx.y * 128;
    const int colBase = blockIdx.x * 128;

    // A-tile (and NT B-tile) load mapping: 256 threads x float4 covers 128x8
    const int arow = tx >> 1;
    const int ac4  = (tx & 1) * 4;
    // NN B-tile load mapping: 8 rows x 128 cols
    const int brow = tx >> 5;
    const int bc4  = (tx & 31) * 4;

    const int row0 = (tx >> 4) * 8;
    const int col0 = (tx & 15) * 8;

    float acc[8][8];
    #pragma unroll
    for (int i = 0; i < 8; i++)
        #pragma unroll
        for (int j = 0; j < 8; j++) acc[i][j] = 0.f;

    const int KT = K >> 3;
    for (int kt = 0; kt < KT; kt++) {
        // load A tile (transposed into shared)
        {
            float4 av = *(const float4*)&A[(size_t)(rowBase + arow) * K + kt * 8 + ac4];
            As[ac4 + 0][arow] = av.x;
            As[ac4 + 1][arow] = av.y;
            As[ac4 + 2][arow] = av.z;
            As[ac4 + 3][arow] = av.w;
        }
        if (TRANSB) {
            float4 bv = *(const float4*)&Bm[(size_t)(colBase + arow) * K + kt * 8 + ac4];
            Bs[ac4 + 0][arow] = bv.x;
            Bs[ac4 + 1][arow] = bv.y;
            Bs[ac4 + 2][arow] = bv.z;
            Bs[ac4 + 3][arow] = bv.w;
        } else {
            float4 bv = *(const float4*)&Bm[(size_t)(kt * 8 + brow) * N + colBase + bc4];
            *(float4*)&Bs[brow][bc4] = bv;
        }
        __syncthreads();

        #pragma unroll
        for (int kk = 0; kk < 8; kk++) {
            float a[8], bb[8];
            *(float4*)(a)      = *(const float4*)&As[kk][row0];
            *(float4*)(a + 4)  = *(const float4*)&As[kk][row0 + 4];
            *(float4*)(bb)     = *(const float4*)&Bs[kk][col0];
            *(float4*)(bb + 4) = *(const float4*)&Bs[kk][col0 + 4];
            #pragma unroll
            for (int i = 0; i < 8; i++)
                #pragma unroll
                for (int j = 0; j < 8; j++)
                    acc[i][j] = fmaf(a[i], bb[j], acc[i][j]);
        }
        __syncthreads();
    }

    const float* mrow = nullptr;
    if (EPI == 2) mrow = extra + (size_t)(bz / HEADS) * maskStride;

    #pragma unroll
    for (int i = 0; i < 8; i++) {
        const int gm = rowBase + row0 + i;
        float vals[8];
        #pragma unroll
        for (int j = 0; j < 8; j++) {
            float v = acc[i][j];
            const int gn = colBase + col0 + j;
            if (EPI == 1) v += extra[gn];
            if (EPI == 2) v = (gn <= gm) ? v * scale + mrow[gn] : -10000.0f;
            vals[j] = v;
        }
        float* crow = &C[(size_t)gm * N + colBase + col0];
        *(float4*)(crow)     = *(const float4*)(vals);
        *(float4*)(crow + 4) = *(const float4*)(vals + 4);
    }
}

// ---------------------------------------------------------------------------
// Softmax over rows of scores [BH*S, S] (causal mask already applied)
// ---------------------------------------------------------------------------
__global__ void __launch_bounds__(256) softmax_kernel(float* __restrict__ p)
{
    float* pr = p + (size_t)blockIdx.x * S_;
    __shared__ float red[8];
    __shared__ float bc;

    // pass 1: max
    float m = -1e30f;
    for (int i = threadIdx.x; i < S_; i += 256) m = fmaxf(m, pr[i]);
    #pragma unroll
    for (int o = 16; o; o >>= 1) m = fmaxf(m, __shfl_xor_sync(0xffffffffu, m, o));
    const int w = threadIdx.x >> 5, l = threadIdx.x & 31;
    if (l == 0) red[w] = m;
    __syncthreads();
    if (threadIdx.x == 0) {
        float mm = red[0];
        #pragma unroll
        for (int i = 1; i < 8; i++) mm = fmaxf(mm, red[i]);
        bc = mm;
    }
    __syncthreads();
    m = bc;

    // pass 2: exp + sum (store exp in place)
    float s = 0.f;
    for (int i = threadIdx.x; i < S_; i += 256) {
        float e = __expf(pr[i] - m);
        pr[i] = e;
        s += e;
    }
    #pragma unroll
    for (int o = 16; o; o >>= 1) s += __shfl_xor_sync(0xffffffffu, s, o);
    if (l == 0) red[w] = s;
    __syncthreads();
    if (threadIdx.x == 0) {
        float ss = 0.f;
        #pragma unroll
        for (int i = 0; i < 8; i++) ss += red[i];
        bc = 1.0f / ss;
    }
    __syncthreads();
    const float inv = bc;

    // pass 3: normalize
    for (int i = threadIdx.x; i < S_; i += 256) pr[i] *= inv;
}

// ---------------------------------------------------------------------------
// Split qkv [B,S,3H] -> q,k,v in [B,HEADS,S,DH]
// ---------------------------------------------------------------------------
__global__ void __launch_bounds__(256) split_qkv(
    const float* __restrict__ qkv,
    float* __restrict__ q, float* __restrict__ k, float* __restrict__ v)
{
    size_t idx = (size_t)blockIdx.x * 256 + threadIdx.x;   // over [b,s,h,d]
    if (idx >= BSH) return;
    const int d = (int)(idx & (DH - 1));
    size_t t = idx >> 7;                                   // (b*S+s)*HEADS + h
    const int h = (int)(t & (HEADS - 1));
    t >>= 4;                                               // b*S + s
    const int s = (int)(t & (S_ - 1));
    const int b = (int)(t >> 11);
    const size_t src = ((size_t)(b * S_ + s)) * (3 * H_) + h * DH + d;
    const size_t dst = (((size_t)(b * HEADS + h)) * S_ + s) * DH + d;
    q[dst] = qkv[src];
    k[dst] = qkv[src + H_];
    v[dst] = qkv[src + 2 * H_];
}

// ---------------------------------------------------------------------------
// Merge ctx heads [B,HEADS,S,DH] -> [B,S,H]
// ---------------------------------------------------------------------------
__global__ void __launch_bounds__(256) merge_ctx(
    const float* __restrict__ ch, float* __restrict__ ctx)
{
    size_t idx = (size_t)blockIdx.x * 256 + threadIdx.x;   // over [b,h,s,d]
    if (idx >= BSH) return;
    const int d = (int)(idx & (DH - 1));
    size_t t = idx >> 7;                                   // (b*HEADS+h)*S + s
    const int s = (int)(t & (S_ - 1));
    t >>= 11;                                              // b*HEADS + h
    const int h = (int)(t & (HEADS - 1));
    const int b = (int)(t >> 4);
    ctx[((size_t)(b * S_ + s)) * H_ + h * DH + d] = ch[idx];
}

// ---------------------------------------------------------------------------
// kernel_launch
// ---------------------------------------------------------------------------
extern "C" void kernel_launch(void* const* d_in, const int* in_sizes, int n_in,
                              void* d_out, int out_size)
{
    const float* x    = (const float*)d_in[0];
    const float* mask = (const float*)d_in[1];
    const float* qkvw = (const float*)d_in[2];
    const float* qkvb = (const float*)d_in[3];
    const float* ow   = (const float*)d_in[4];
    const float* nw   = (const float*)d_in[5];
    const float* nb   = (const float*)d_in[6];

    float* out     = (float*)d_out;
    float* out_o   = out;                 // [B,S,H]
    float* out_k   = out + 1 * BSH;       // [B,HEADS,S,DH]
    float* out_v   = out + 2 * BSH;       // [B,HEADS,S,DH]
    float* out_ctx = out + 3 * BSH;       // [B,S,H]
    float* out_ln  = out + 4 * BSH;       // [B,S,H]

    float *qkv, *q, *scores, *ctxh;
    cudaGetSymbolAddress((void**)&qkv,    g_qkv);
    cudaGetSymbolAddress((void**)&q,      g_q);
    cudaGetSymbolAddress((void**)&scores, g_scores);
    cudaGetSymbolAddress((void**)&ctxh,   g_ctxh);

    const float scale = 1.0f / sqrtf((float)DH);   // q,k each scaled by dh^-0.25

    // 1. LayerNorm -> out_ln (also the QKV GEMM input)
    ln_kernel<<<B_ * S_, 256>>>(x, nw, nb, out_ln);

    // 2. QKV GEMM: [4096,2048] @ [2048,6144] + bias
    sgemm<false, 1><<<dim3(3 * H_ / 128, B_ * S_ / 128, 1), 256>>>(
        out_ln, qkvw, qkv, B_ * S_, 3 * H_, H_, 0, 0, 0, qkvb, 1.0f, 0);

    // 3. Split into q (scratch), k/v (directly into outputs)
    split_qkv<<<(unsigned)(BSH / 256), 256>>>(qkv, q, out_k, out_v);

    // 4. Scores: per (b,h): Q[S,dh] @ K^T -> [S,S], fused scale+mask+causal
    sgemm<true, 2><<<dim3(S_ / 128, S_ / 128, BH), 256>>>(
        q, out_k, scores, S_, S_, DH,
        (size_t)S_ * DH, (size_t)S_ * DH, (size_t)S_ * S_,
        mask, scale, S_);

    // 5. Softmax rows
    softmax_kernel<<<BH * S_, 256>>>(scores);

    // 6. ctx: probs[S,S] @ V[S,dh]
    sgemm<false, 0><<<dim3(1, S_ / 128, BH), 256>>>(
        scores, out_v, ctxh, S_, DH, S_,
        (size_t)S_ * S_, (size_t)S_ * DH, (size_t)S_ * DH,
        nullptr, 1.0f, 0);

    // 7. Merge heads -> out_ctx
    merge_ctx<<<(unsigned)(BSH / 256), 256>>>(ctxh, out_ctx);

    // 8. Output projection: ctx[4096,2048] @ ow[2048,2048]
    sgemm<false, 0><<<dim3(H_ / 128, B_ * S_ / 128, 1), 256>>>(
        out_ctx, ow, out_o, B_ * S_, H_, H_, 0, 0, 0, nullptr, 1.0f, 0);
}

// round 2
// speedup vs baseline: 3.6715x; 3.6715x over previous
#include <cuda_runtime.h>
#include <cstdint>
#include <math.h>

// Problem constants (fixed by the reference setup)
#define B_    2
#define S_    2048
#define H_    2048
#define HEADS 16
#define DH    128
#define BH    (B_*HEADS)
#define BSH   ((size_t)B_*S_*H_)

// ---------------------------------------------------------------------------
// Scratch (static device globals — no allocation in kernel_launch)
// ---------------------------------------------------------------------------
__device__ float g_qkv[(size_t)B_*S_*3*H_];
__device__ float g_q[BSH];
__device__ float g_scores[(size_t)BH*S_*S_];
__device__ float g_ctxh[BSH];

// ---------------------------------------------------------------------------
// Small helpers
// ---------------------------------------------------------------------------
__device__ __forceinline__ uint32_t f2tf(float f) {
    uint32_t r;
    asm("cvt.rna.tf32.f32 %0, %1;" : "=r"(r) : "f"(f));
    return r;
}

__device__ __forceinline__ void mma_tf32(float* c, const uint32_t* a, const uint32_t* b) {
    asm volatile(
        "mma.sync.aligned.m16n8k8.row.col.f32.tf32.tf32.f32 "
        "{%0,%1,%2,%3},{%4,%5,%6,%7},{%8,%9},{%0,%1,%2,%3};\n"
        : "+f"(c[0]), "+f"(c[1]), "+f"(c[2]), "+f"(c[3])
        : "r"(a[0]), "r"(a[1]), "r"(a[2]), "r"(a[3]), "r"(b[0]), "r"(b[1]));
}

__device__ __forceinline__ void cp16(uint32_t dst, const float* src) {
    asm volatile("cp.async.cg.shared.global [%0], [%1], 16;\n" :: "r"(dst), "l"(src));
}
#define CP_COMMIT() asm volatile("cp.async.commit_group;\n")
#define CP_WAIT0()  asm volatile("cp.async.wait_group 0;\n")

// ---------------------------------------------------------------------------
// LayerNorm: one block per row of x [B*S, H]
// ---------------------------------------------------------------------------
__global__ void __launch_bounds__(256) ln_kernel(
    const float* __restrict__ x, const float* __restrict__ g,
    const float* __restrict__ b, float* __restrict__ y)
{
    const size_t row = blockIdx.x;
    const float* xr = x + row * H_;
    float s = 0.f, ss = 0.f;
    for (int i = threadIdx.x; i < H_; i += 256) {
        float t = xr[i];
        s += t; ss += t * t;
    }
    #pragma unroll
    for (int o = 16; o; o >>= 1) {
        s  += __shfl_xor_sync(0xffffffffu, s,  o);
        ss += __shfl_xor_sync(0xffffffffu, ss, o);
    }
    __shared__ float red[2][8];
    const int w = threadIdx.x >> 5, l = threadIdx.x & 31;
    if (l == 0) { red[0][w] = s; red[1][w] = ss; }
    __syncthreads();
    __shared__ float stats[2];
    if (threadIdx.x == 0) {
        float S = 0.f, SS = 0.f;
        #pragma unroll
        for (int i = 0; i < 8; i++) { S += red[0][i]; SS += red[1][i]; }
        float mu  = S / (float)H_;
        float var = SS / (float)H_ - mu * mu;
        stats[0] = mu;
        stats[1] = rsqrtf(var + 1e-12f);
    }
    __syncthreads();
    const float mu = stats[0], rstd = stats[1];
    float* yr = y + row * H_;
    for (int i = threadIdx.x; i < H_; i += 256)
        yr[i] = (xr[i] - mu) * rstd * g[i] + b[i];
}

// ---------------------------------------------------------------------------
// TF32 tensor-core GEMM: C[M,N] = A[M,K] @ B   (NN: B[K,N]; NT: B[N,K] -> B^T)
// CTA tile 128x128, K-tile 32, 256 threads (8 warps, each 64x32 warp tile),
// cp.async double-buffered. Batched via blockIdx.z strides.
// EPI: 0 plain, 1 +bias[n], 2 attention epilogue (causal + scale + mask).
// CSKIP: skip blocks strictly above diagonal (fill -10000).
// CK:    truncate K loop at diagonal (probs @ V, upper triangle exactly 0).
// ---------------------------------------------------------------------------
template<bool TRANSB, int EPI, bool CSKIP, bool CK>
__global__ void __launch_bounds__(256) mma_gemm(
    const float* __restrict__ A, const float* __restrict__ Bm,
    float* __restrict__ C, int M, int N, int K,
    size_t sA, size_t sB, size_t sC,
    const float* __restrict__ extra, float scale, int maskStride)
{
    const int bz = blockIdx.z;
    A  += (size_t)bz * sA;
    Bm += (size_t)bz * sB;
    C  += (size_t)bz * sC;

    const int rowBase = blockIdx.y * 128;
    const int colBase = blockIdx.x * 128;
    const int tx = threadIdx.x;

    if (CSKIP && colBase > rowBase + 127) {
        // Entire tile above causal diagonal: fill with MINUS_INF.
        const int c4 = (tx & 31) * 4;
        const int r0 = tx >> 5;
        const float4 f = make_float4(-10000.f, -10000.f, -10000.f, -10000.f);
        #pragma unroll
        for (int i = 0; i < 16; i++)
            *(float4*)&C[(size_t)(rowBase + r0 + i * 8) * N + colBase + c4] = f;
        return;
    }

    extern __shared__ float sm[];
    float* A_s = sm;                         // [2][128][36]
    float* B_s = sm + 2 * 128 * 36;          // NN: [2][32][136]  NT: [2][128][36]
    const int ASTAGE = 128 * 36;
    const int BSTAGE = TRANSB ? 128 * 36 : 32 * 136;

    const int lane = tx & 31, warp = tx >> 5;
    const int wm = (warp >> 2) * 64;   // 0 or 64
    const int wn = (warp & 3) * 32;    // 0..96
    const int lr = lane >> 2;          // 0..7
    const int lc = lane & 3;           // 0..3

    // Loader mappings
    const int aRow  = tx >> 3;          // 0..31 (A & NT-B tiles, +32*i)
    const int aCol4 = (tx & 7) * 4;
    const int bRow  = tx >> 5;          // 0..7  (NN-B tile, +8*i)
    const int bCol4 = (tx & 31) * 4;

    const uint32_t sAaddr = (uint32_t)__cvta_generic_to_shared(&A_s[aRow * 36 + aCol4]);
    uint32_t sBaddr;
    if (TRANSB) sBaddr = (uint32_t)__cvta_generic_to_shared(&B_s[aRow * 36 + aCol4]);
    else        sBaddr = (uint32_t)__cvta_generic_to_shared(&B_s[bRow * 136 + bCol4]);

    const float* gA0 = A + (size_t)(rowBase + aRow) * K + aCol4;
    const float* gB0;
    if (TRANSB) gB0 = Bm + (size_t)(colBase + aRow) * K + aCol4;
    else        gB0 = Bm + (size_t)bRow * N + colBase + bCol4;

    int ktEnd = K >> 5;
    if (CK) {
        int lim = (rowBase >> 5) + 4;   // cover k <= rowBase+127
        if (lim < ktEnd) ktEnd = lim;
    }

    float acc[4][4][4];
    #pragma unroll
    for (int i = 0; i < 4; i++)
        #pragma unroll
        for (int j = 0; j < 4; j++)
            #pragma unroll
            for (int r = 0; r < 4; r++) acc[i][j][r] = 0.f;

    auto load = [&](int kt, int buf) {
        const float* ga = gA0 + kt * 32;
        uint32_t da = sAaddr + buf * ASTAGE * 4;
        #pragma unroll
        for (int i = 0; i < 4; i++)
            cp16(da + i * 32 * 36 * 4, ga + (size_t)i * 32 * K);
        if (TRANSB) {
            const float* gb = gB0 + kt * 32;
            uint32_t db = sBaddr + buf * BSTAGE * 4;
            #pragma unroll
            for (int i = 0; i < 4; i++)
                cp16(db + i * 32 * 36 * 4, gb + (size_t)i * 32 * K);
        } else {
            const float* gb = gB0 + (size_t)kt * 32 * N;
            uint32_t db = sBaddr + buf * BSTAGE * 4;
            #pragma unroll
            for (int i = 0; i < 4; i++)
                cp16(db + i * 8 * 136 * 4, gb + (size_t)i * 8 * N);
        }
    };

    load(0, 0);
    CP_COMMIT();

    for (int kt = 0; kt < ktEnd; kt++) {
        CP_WAIT0();
        __syncthreads();
        if (kt + 1 < ktEnd) { load(kt + 1, (kt + 1) & 1); CP_COMMIT(); }

        const float* As = A_s + (kt & 1) * ASTAGE;
        const float* Bs = B_s + (kt & 1) * BSTAGE;

        #pragma unroll
        for (int ks = 0; ks < 4; ks++) {
            uint32_t af[4][4];
            #pragma unroll
            for (int mt = 0; mt < 4; mt++) {
                const float* p = As + (wm + mt * 16 + lr) * 36 + ks * 8 + lc;
                af[mt][0] = f2tf(p[0]);
                af[mt][1] = f2tf(p[8 * 36]);
                af[mt][2] = f2tf(p[4]);
                af[mt][3] = f2tf(p[8 * 36 + 4]);
            }
            uint32_t bf[4][2];
            #pragma unroll
            for (int nt = 0; nt < 4; nt++) {
                const int n = wn + nt * 8 + lr;
                if (TRANSB) {
                    const float* p = Bs + n * 36 + ks * 8 + lc;
                    bf[nt][0] = f2tf(p[0]);
                    bf[nt][1] = f2tf(p[4]);
                } else {
                    const float* p = Bs + (ks * 8 + lc) * 136 + n;
                    bf[nt][0] = f2tf(p[0]);
                    bf[nt][1] = f2tf(p[4 * 136]);
                }
            }
            #pragma unroll
            for (int mt = 0; mt < 4; mt++)
                #pragma unroll
                for (int nt = 0; nt < 4; nt++)
                    mma_tf32(acc[mt][nt], af[mt], bf[nt]);
        }
    }

    // Epilogue
    const float* mrow = (EPI == 2) ? (extra + (size_t)(bz / HEADS) * maskStride) : nullptr;
    #pragma unroll
    for (int mt = 0; mt < 4; mt++) {
        #pragma unroll
        for (int nt = 0; nt < 4; nt++) {
            const int gm = rowBase + wm + mt * 16 + lr;
            const int gn = colBase + wn + nt * 8 + 2 * lc;
            float* a = acc[mt][nt];
            #pragma unroll
            for (int r = 0; r < 2; r++) {
                const int row = gm + r * 8;
                float v0 = a[r * 2 + 0];
                float v1 = a[r * 2 + 1];
                if (EPI == 1) { v0 += extra[gn]; v1 += extra[gn + 1]; }
                if (EPI == 2) {
                    v0 = (gn     <= row) ? v0 * scale + mrow[gn]     : -10000.f;
                    v1 = (gn + 1 <= row) ? v1 * scale + mrow[gn + 1] : -10000.f;
                }
                float2 out2 = make_float2(v0, v1);
                *(float2*)&C[(size_t)row * N + gn] = out2;
            }
        }
    }
}

// ---------------------------------------------------------------------------
// Single-pass register-resident softmax over rows [BH*S, S_]
// ---------------------------------------------------------------------------
__global__ void __launch_bounds__(256) softmax_kernel(float* __restrict__ p)
{
    float* pr = p + (size_t)blockIdx.x * S_;
    const int tx = threadIdx.x;
    __shared__ float red[8];
    __shared__ float bc;

    float v[8];
    float m = -3.4e38f;
    #pragma unroll
    for (int j = 0; j < 8; j++) {
        v[j] = pr[tx + j * 256];
        m = fmaxf(m, v[j]);
    }
    #pragma unroll
    for (int o = 16; o; o >>= 1) m = fmaxf(m, __shfl_xor_sync(0xffffffffu, m, o));
    const int w = tx >> 5, l = tx & 31;
    if (l == 0) red[w] = m;
    __syncthreads();
    if (tx == 0) {
        float mm = red[0];
        #pragma unroll
        for (int i = 1; i < 8; i++) mm = fmaxf(mm, red[i]);
        bc = mm;
    }
    __syncthreads();
    m = bc;

    float s = 0.f;
    #pragma unroll
    for (int j = 0; j < 8; j++) {
        v[j] = __expf(v[j] - m);
        s += v[j];
    }
    #pragma unroll
    for (int o = 16; o; o >>= 1) s += __shfl_xor_sync(0xffffffffu, s, o);
    if (l == 0) red[w] = s;
    __syncthreads();
    if (tx == 0) {
        float ss = 0.f;
        #pragma unroll
        for (int i = 0; i < 8; i++) ss += red[i];
        bc = 1.0f / ss;
    }
    __syncthreads();
    const float inv = bc;
    #pragma unroll
    for (int j = 0; j < 8; j++) pr[tx + j * 256] = v[j] * inv;
}

// ---------------------------------------------------------------------------
// Split qkv [B,S,3H] -> q,k,v in [B,HEADS,S,DH]
// ---------------------------------------------------------------------------
__global__ void __launch_bounds__(256) split_qkv(
    const float* __restrict__ qkv,
    float* __restrict__ q, float* __restrict__ k, float* __restrict__ v)
{
    size_t idx = (size_t)blockIdx.x * 256 + threadIdx.x;
    if (idx >= BSH) return;
    const int d = (int)(idx & (DH - 1));
    size_t t = idx >> 7;
    const int h = (int)(t & (HEADS - 1));
    t >>= 4;
    const int s = (int)(t & (S_ - 1));
    const int b = (int)(t >> 11);
    const size_t src = ((size_t)(b * S_ + s)) * (3 * H_) + h * DH + d;
    const size_t dst = (((size_t)(b * HEADS + h)) * S_ + s) * DH + d;
    q[dst] = qkv[src];
    k[dst] = qkv[src + H_];
    v[dst] = qkv[src + 2 * H_];
}

// ---------------------------------------------------------------------------
// Merge ctx heads [B,HEADS,S,DH] -> [B,S,H]
// ---------------------------------------------------------------------------
__global__ void __launch_bounds__(256) merge_ctx(
    const float* __restrict__ ch, float* __restrict__ ctx)
{
    size_t idx = (size_t)blockIdx.x * 256 + threadIdx.x;
    if (idx >= BSH) return;
    const int d = (int)(idx & (DH - 1));
    size_t t = idx >> 7;
    const int s = (int)(t & (S_ - 1));
    t >>= 11;
    const int h = (int)(t & (HEADS - 1));
    const int b = (int)(t >> 4);
    ctx[((size_t)(b * S_ + s)) * H_ + h * DH + d] = ch[idx];
}

// ---------------------------------------------------------------------------
// kernel_launch
// ---------------------------------------------------------------------------
extern "C" void kernel_launch(void* const* d_in, const int* in_sizes, int n_in,
                              void* d_out, int out_size)
{
    const float* x    = (const float*)d_in[0];
    const float* mask = (const float*)d_in[1];
    const float* qkvw = (const float*)d_in[2];
    const float* qkvb = (const float*)d_in[3];
    const float* ow   = (const float*)d_in[4];
    const float* nw   = (const float*)d_in[5];
    const float* nb   = (const float*)d_in[6];

    float* out     = (float*)d_out;
    float* out_o   = out;
    float* out_k   = out + 1 * BSH;
    float* out_v   = out + 2 * BSH;
    float* out_ctx = out + 3 * BSH;
    float* out_ln  = out + 4 * BSH;

    float *qkv, *q, *scores, *ctxh;
    cudaGetSymbolAddress((void**)&qkv,    g_qkv);
    cudaGetSymbolAddress((void**)&q,      g_q);
    cudaGetSymbolAddress((void**)&scores, g_scores);
    cudaGetSymbolAddress((void**)&ctxh,   g_ctxh);

    const int SMEM = (2 * 128 * 36 + 2 * 128 * 36) * 4;   // 73728 B (max of NN/NT)

    cudaFuncSetAttribute(mma_gemm<false, 1, false, false>,
                         cudaFuncAttributeMaxDynamicSharedMemorySize, SMEM);
    cudaFuncSetAttribute(mma_gemm<true, 2, true, false>,
                         cudaFuncAttributeMaxDynamicSharedMemorySize, SMEM);
    cudaFuncSetAttribute(mma_gemm<false, 0, false, true>,
                         cudaFuncAttributeMaxDynamicSharedMemorySize, SMEM);
    cudaFuncSetAttribute(mma_gemm<false, 0, false, false>,
                         cudaFuncAttributeMaxDynamicSharedMemorySize, SMEM);

    const float scale = 1.0f / sqrtf((float)DH);

    // 1. LayerNorm -> out_ln
    ln_kernel<<<B_ * S_, 256>>>(x, nw, nb, out_ln);

    // 2. QKV GEMM + bias: [4096,2048] @ [2048,6144]
    mma_gemm<false, 1, false, false><<<dim3(3 * H_ / 128, B_ * S_ / 128, 1), 256, SMEM>>>(
        out_ln, qkvw, qkv, B_ * S_, 3 * H_, H_, 0, 0, 0, qkvb, 1.0f, 0);

    // 3. Split q/k/v
    split_qkv<<<(unsigned)(BSH / 256), 256>>>(qkv, q, out_k, out_v);

    // 4. Scores: Q @ K^T, fused scale+mask+causal, upper blocks skipped
    mma_gemm<true, 2, true, false><<<dim3(S_ / 128, S_ / 128, BH), 256, SMEM>>>(
        q, out_k, scores, S_, S_, DH,
        (size_t)S_ * DH, (size_t)S_ * DH, (size_t)S_ * S_,
        mask, scale, S_);

    // 5. Softmax
    softmax_kernel<<<BH * S_, 256>>>(scores);

    // 6. ctx: probs @ V, K-loop truncated at the causal diagonal
    mma_gemm<false, 0, false, true><<<dim3(1, S_ / 128, BH), 256, SMEM>>>(
        scores, out_v, ctxh, S_, DH, S_,
        (size_t)S_ * S_, (size_t)S_ * DH, (size_t)S_ * DH,
        nullptr, 1.0f, 0);

    // 7. Merge heads
    merge_ctx<<<(unsigned)(BSH / 256), 256>>>(ctxh, out_ctx);

    // 8. Output projection
    mma_gemm<false, 0, false, false><<<dim3(H_ / 128, B_ * S_ / 128, 1), 256, SMEM>>>(
        out_ctx, ow, out_o, B_ * S_, H_, H_, 0, 0, 0, nullptr, 1.0f, 0);
}

// round 3
// speedup vs baseline: 4.3032x; 1.1721x over previous
#include <cuda_runtime.h>
#include <cstdint>
#include <math.h>

#define B_    2
#define S_    2048
#define H_    2048
#define HEADS 16
#define DH    128
#define BH    (B_*HEADS)
#define BSH   ((size_t)B_*S_*H_)

// ---------------------------------------------------------------------------
// Scratch
// ---------------------------------------------------------------------------
__device__ float g_q[BSH];                    // [B,HEADS,S,DH]
__device__ float g_scores[(size_t)BH*S_*S_];  // [BH,S,S]

// ---------------------------------------------------------------------------
// Helpers
// ---------------------------------------------------------------------------
__device__ __forceinline__ uint32_t f2tf(float f) {
    uint32_t r;
    asm("cvt.rna.tf32.f32 %0, %1;" : "=r"(r) : "f"(f));
    return r;
}
__device__ __forceinline__ void mma_tf32(float* c, const uint32_t* a, const uint32_t* b) {
    asm volatile(
        "mma.sync.aligned.m16n8k8.row.col.f32.tf32.tf32.f32 "
        "{%0,%1,%2,%3},{%4,%5,%6,%7},{%8,%9},{%0,%1,%2,%3};\n"
        : "+f"(c[0]), "+f"(c[1]), "+f"(c[2]), "+f"(c[3])
        : "r"(a[0]), "r"(a[1]), "r"(a[2]), "r"(a[3]), "r"(b[0]), "r"(b[1]));
}
__device__ __forceinline__ void cp16(uint32_t dst, const float* src) {
    asm volatile("cp.async.cg.shared.global [%0], [%1], 16;\n" :: "r"(dst), "l"(src));
}
#define CP_COMMIT() asm volatile("cp.async.commit_group;\n")
#define CP_WAIT0()  asm volatile("cp.async.wait_group 0;\n")

// ---------------------------------------------------------------------------
// LayerNorm
// ---------------------------------------------------------------------------
__global__ void __launch_bounds__(256) ln_kernel(
    const float* __restrict__ x, const float* __restrict__ g,
    const float* __restrict__ b, float* __restrict__ y)
{
    const size_t row = blockIdx.x;
    const float* xr = x + row * H_;
    float s = 0.f, ss = 0.f;
    for (int i = threadIdx.x; i < H_; i += 256) {
        float t = xr[i];
        s += t; ss += t * t;
    }
    #pragma unroll
    for (int o = 16; o; o >>= 1) {
        s  += __shfl_xor_sync(0xffffffffu, s,  o);
        ss += __shfl_xor_sync(0xffffffffu, ss, o);
    }
    __shared__ float red[2][8];
    const int w = threadIdx.x >> 5, l = threadIdx.x & 31;
    if (l == 0) { red[0][w] = s; red[1][w] = ss; }
    __syncthreads();
    __shared__ float stats[2];
    if (threadIdx.x == 0) {
        float S = 0.f, SS = 0.f;
        #pragma unroll
        for (int i = 0; i < 8; i++) { S += red[0][i]; SS += red[1][i]; }
        float mu  = S / (float)H_;
        float var = SS / (float)H_ - mu * mu;
        stats[0] = mu;
        stats[1] = rsqrtf(var + 1e-12f);
    }
    __syncthreads();
    const float mu = stats[0], rstd = stats[1];
    float* yr = y + row * H_;
    for (int i = threadIdx.x; i < H_; i += 256)
        yr[i] = (xr[i] - mu) * rstd * g[i] + b[i];
}

// ---------------------------------------------------------------------------
// TF32 tensor-core GEMM, 128x128 CTA tile, K-tile 32, 256 threads.
// A staged LDG->cvt->STS (tf32 bits in smem); B via cp.async (raw floats,
// cvt at fragment load). Double-buffered.
// EPI: 0 plain, 2 attention epilogue, 3 qkv-scatter(+bias)
// CSKIP: early-return blocks strictly above causal diagonal (no fill)
// CK:    truncate K loop at diagonal
// CTXW:  write C merged as [B,S,H] (per-bz head offset, ldC=H_)
// ---------------------------------------------------------------------------
template<bool TRANSB, int EPI, bool CSKIP, bool CK, bool CTXW>
__global__ void __launch_bounds__(256, 2) mma_gemm(
    const float* __restrict__ A, const float* __restrict__ Bm,
    float* __restrict__ C,
    float* __restrict__ Cq, float* __restrict__ Ckk, float* __restrict__ Cv,
    int M, int N, int K, size_t sA, size_t sB, size_t sC,
    const float* __restrict__ extra, float scale, int maskStride)
{
    const int rowBase = blockIdx.y * 128;
    const int colBase = blockIdx.x * 128;
    if (CSKIP && colBase > rowBase + 127) return;   // never read downstream

    const int bz = blockIdx.z;
    A  += (size_t)bz * sA;
    Bm += (size_t)bz * sB;
    int ldC = N;
    if (CTXW) {
        C  += (size_t)(bz >> 4) * S_ * H_ + (size_t)(bz & 15) * DH;
        ldC = H_;
    } else {
        C  += (size_t)bz * sC;
    }

    extern __shared__ uint32_t sm4[];
    uint32_t* A_s = sm4;                                  // [2][128][36] tf32
    float*    B_s = (float*)(sm4 + 2 * 128 * 36);         // NN [2][32][136] / NT [2][128][36]
    const int ASTAGE = 128 * 36;
    const int BSTAGE = TRANSB ? 128 * 36 : 32 * 136;

    const int tx = threadIdx.x;
    const int lane = tx & 31, warp = tx >> 5;
    const int wm = (warp >> 2) * 64;
    const int wn = (warp & 3) * 32;
    const int lr = lane >> 2;
    const int lc = lane & 3;

    const int aRow  = tx >> 3;          // 0..31
    const int aCol4 = (tx & 7) * 4;
    const int bRow  = tx >> 5;          // 0..7 (NN B)
    const int bCol4 = (tx & 31) * 4;

    uint32_t sBaddr;
    if (TRANSB) sBaddr = (uint32_t)__cvta_generic_to_shared(&B_s[aRow * 36 + aCol4]);
    else        sBaddr = (uint32_t)__cvta_generic_to_shared(&B_s[bRow * 136 + bCol4]);

    const float* gA0 = A + (size_t)(rowBase + aRow) * K + aCol4;
    const float* gB0;
    if (TRANSB) gB0 = Bm + (size_t)(colBase + aRow) * K + aCol4;
    else        gB0 = Bm + (size_t)bRow * N + colBase + bCol4;

    int ktEnd = K >> 5;
    if (CK) {
        int lim = (rowBase >> 5) + 4;
        if (lim < ktEnd) ktEnd = lim;
    }

    float acc[4][4][4];
    #pragma unroll
    for (int i = 0; i < 4; i++)
        #pragma unroll
        for (int j = 0; j < 4; j++)
            #pragma unroll
            for (int r = 0; r < 4; r++) acc[i][j][r] = 0.f;

    float4 ra[4];
    auto ldgA = [&](int kt) {
        #pragma unroll
        for (int i = 0; i < 4; i++)
            ra[i] = *(const float4*)(gA0 + kt * 32 + (size_t)i * 32 * K);
    };
    auto stsA = [&](int buf) {
        uint32_t* dst = A_s + buf * ASTAGE + aRow * 36 + aCol4;
        #pragma unroll
        for (int i = 0; i < 4; i++) {
            uint4 u;
            u.x = f2tf(ra[i].x); u.y = f2tf(ra[i].y);
            u.z = f2tf(ra[i].z); u.w = f2tf(ra[i].w);
            *(uint4*)(dst + i * 32 * 36) = u;
        }
    };
    auto cpB = [&](int kt, int buf) {
        uint32_t db = sBaddr + buf * BSTAGE * 4;
        if (TRANSB) {
            const float* gb = gB0 + kt * 32;
            #pragma unroll
            for (int i = 0; i < 4; i++)
                cp16(db + i * 32 * 36 * 4, gb + (size_t)i * 32 * K);
        } else {
            const float* gb = gB0 + (size_t)kt * 32 * N;
            #pragma unroll
            for (int i = 0; i < 4; i++)
                cp16(db + i * 8 * 136 * 4, gb + (size_t)i * 8 * N);
        }
    };

    // prologue
    ldgA(0);
    cpB(0, 0); CP_COMMIT();
    stsA(0);
    CP_WAIT0();
    __syncthreads();

    for (int kt = 0; kt < ktEnd; kt++) {
        const int buf = kt & 1;
        const bool more = (kt + 1 < ktEnd);
        if (more) {
            ldgA(kt + 1);
            cpB(kt + 1, buf ^ 1); CP_COMMIT();
        }

        const uint32_t* As = A_s + buf * ASTAGE;
        const float*    Bs = B_s + buf * BSTAGE;

        #pragma unroll
        for (int ks = 0; ks < 4; ks++) {
            uint32_t af[4][4];
            #pragma unroll
            for (int mt = 0; mt < 4; mt++) {
                const uint32_t* p = As + (wm + mt * 16 + lr) * 36 + ks * 8 + lc;
                af[mt][0] = p[0];
                af[mt][1] = p[8 * 36];
                af[mt][2] = p[4];
                af[mt][3] = p[8 * 36 + 4];
            }
            uint32_t bf[4][2];
            #pragma unroll
            for (int nt = 0; nt < 4; nt++) {
                const int n = wn + nt * 8 + lr;
                if (TRANSB) {
                    const float* p = Bs + n * 36 + ks * 8 + lc;
                    bf[nt][0] = f2tf(p[0]);
                    bf[nt][1] = f2tf(p[4]);
                } else {
                    const float* p = Bs + (ks * 8 + lc) * 136 + n;
                    bf[nt][0] = f2tf(p[0]);
                    bf[nt][1] = f2tf(p[4 * 136]);
                }
            }
            #pragma unroll
            for (int mt = 0; mt < 4; mt++)
                #pragma unroll
                for (int nt = 0; nt < 4; nt++)
                    mma_tf32(acc[mt][nt], af[mt], bf[nt]);
        }

        if (more) {
            stsA(buf ^ 1);
            CP_WAIT0();
            __syncthreads();
        }
    }

    // ---------------- epilogue ----------------
    if (EPI == 3) {
        // QKV scatter: col block [colBase,colBase+128) is one head of one of q/k/v
        const int whichBlk = colBase >> 11;
        float* base = (whichBlk == 0) ? Cq : (whichBlk == 1) ? Ckk : Cv;
        const int h = (colBase & 2047) >> 7;
        #pragma unroll
        for (int mt = 0; mt < 4; mt++) {
            #pragma unroll
            for (int nt = 0; nt < 4; nt++) {
                const int d  = wn + nt * 8 + 2 * lc;
                const int gn = colBase + d;
                float* a = acc[mt][nt];
                #pragma unroll
                for (int r = 0; r < 2; r++) {
                    const int m = rowBase + wm + mt * 16 + lr + r * 8;
                    const int b = m >> 11, s = m & 2047;
                    float2 o2 = make_float2(a[r * 2 + 0] + extra[gn],
                                            a[r * 2 + 1] + extra[gn + 1]);
                    *(float2*)&base[((((size_t)b * 16 + h) << 11) + s) * 128 + d] = o2;
                }
            }
        }
        return;
    }

    const float* mrow = (EPI == 2) ? (extra + (size_t)(bz / HEADS) * maskStride) : nullptr;
    #pragma unroll
    for (int mt = 0; mt < 4; mt++) {
        #pragma unroll
        for (int nt = 0; nt < 4; nt++) {
            const int gm = rowBase + wm + mt * 16 + lr;
            const int gn = colBase + wn + nt * 8 + 2 * lc;
            float* a = acc[mt][nt];
            #pragma unroll
            for (int r = 0; r < 2; r++) {
                const int row = gm + r * 8;
                float v0 = a[r * 2 + 0];
                float v1 = a[r * 2 + 1];
                if (EPI == 2) {
                    v0 = (gn     <= row) ? v0 * scale + mrow[gn]     : -10000.f;
                    v1 = (gn + 1 <= row) ? v1 * scale + mrow[gn + 1] : -10000.f;
                }
                *(float2*)&C[(size_t)row * ldC + gn] = make_float2(v0, v1);
            }
        }
    }
}

// ---------------------------------------------------------------------------
// Prefix softmax: row s only has valid data in [0, L), L=(floor(s/128)+1)*128.
// float4 I/O, register-resident.
// ---------------------------------------------------------------------------
__global__ void __launch_bounds__(256) softmax_kernel(float* __restrict__ p)
{
    const int s  = blockIdx.x;
    const int bh = blockIdx.y;
    const int L4 = (((s >> 7) + 1) << 7) >> 2;     // row length in float4s
    float4* pr = (float4*)(p + ((size_t)bh * S_ + s) * S_);
    const int tx = threadIdx.x;
    __shared__ float red[8];
    __shared__ float bc;

    float4 v[2];
    float m = -1e30f;
    #pragma unroll
    for (int j = 0; j < 2; j++) {
        const int idx = tx + j * 256;
        if (idx < L4) {
            v[j] = pr[idx];
            m = fmaxf(fmaxf(fmaxf(m, v[j].x), fmaxf(v[j].y, v[j].z)), v[j].w);
        } else {
            v[j] = make_float4(-1e30f, -1e30f, -1e30f, -1e30f);
        }
    }
    #pragma unroll
    for (int o = 16; o; o >>= 1) m = fmaxf(m, __shfl_xor_sync(0xffffffffu, m, o));
    const int w = tx >> 5, l = tx & 31;
    if (l == 0) red[w] = m;
    __syncthreads();
    if (tx == 0) {
        float mm = red[0];
        #pragma unroll
        for (int i = 1; i < 8; i++) mm = fmaxf(mm, red[i]);
        bc = mm;
    }
    __syncthreads();
    m = bc;

    float ssum = 0.f;
    #pragma unroll
    for (int j = 0; j < 2; j++) {
        v[j].x = __expf(v[j].x - m); ssum += v[j].x;
        v[j].y = __expf(v[j].y - m); ssum += v[j].y;
        v[j].z = __expf(v[j].z - m); ssum += v[j].z;
        v[j].w = __expf(v[j].w - m); ssum += v[j].w;
    }
    #pragma unroll
    for (int o = 16; o; o >>= 1) ssum += __shfl_xor_sync(0xffffffffu, ssum, o);
    if (l == 0) red[w] = ssum;
    __syncthreads();
    if (tx == 0) {
        float t = 0.f;
        #pragma unroll
        for (int i = 0; i < 8; i++) t += red[i];
        bc = 1.0f / t;
    }
    __syncthreads();
    const float inv = bc;
    #pragma unroll
    for (int j = 0; j < 2; j++) {
        const int idx = tx + j * 256;
        if (idx < L4) {
            v[j].x *= inv; v[j].y *= inv; v[j].z *= inv; v[j].w *= inv;
            pr[idx] = v[j];
        }
    }
}

// ---------------------------------------------------------------------------
// kernel_launch
// ---------------------------------------------------------------------------
extern "C" void kernel_launch(void* const* d_in, const int* in_sizes, int n_in,
                              void* d_out, int out_size)
{
    const float* x    = (const float*)d_in[0];
    const float* mask = (const float*)d_in[1];
    const float* qkvw = (const float*)d_in[2];
    const float* qkvb = (const float*)d_in[3];
    const float* ow   = (const float*)d_in[4];
    const float* nw   = (const float*)d_in[5];
    const float* nb   = (const float*)d_in[6];

    float* out     = (float*)d_out;
    float* out_o   = out;
    float* out_k   = out + 1 * BSH;
    float* out_v   = out + 2 * BSH;
    float* out_ctx = out + 3 * BSH;
    float* out_ln  = out + 4 * BSH;

    float *q, *scores;
    cudaGetSymbolAddress((void**)&q,      g_q);
    cudaGetSymbolAddress((void**)&scores, g_scores);

    const int SMEM = (2 * 128 * 36 + 2 * 128 * 36) * 4;   // 73728 B

    cudaFuncSetAttribute(mma_gemm<false, 3, false, false, false>,
                         cudaFuncAttributeMaxDynamicSharedMemorySize, SMEM);
    cudaFuncSetAttribute(mma_gemm<true, 2, true, false, false>,
                         cudaFuncAttributeMaxDynamicSharedMemorySize, SMEM);
    cudaFuncSetAttribute(mma_gemm<false, 0, false, true, true>,
                         cudaFuncAttributeMaxDynamicSharedMemorySize, SMEM);
    cudaFuncSetAttribute(mma_gemm<false, 0, false, false, false>,
                         cudaFuncAttributeMaxDynamicSharedMemorySize, SMEM);

    const float scale = 1.0f / sqrtf((float)DH);

    // 1. LayerNorm -> out_ln
    ln_kernel<<<B_ * S_, 256>>>(x, nw, nb, out_ln);

    // 2. QKV GEMM + bias, scattering q->g_q, k->out_k, v->out_v in [B,H,S,dh]
    mma_gemm<false, 3, false, false, false><<<dim3(48, 32, 1), 256, SMEM>>>(
        out_ln, qkvw, nullptr, q, out_k, out_v,
        B_ * S_, 3 * H_, H_, 0, 0, 0, qkvb, 1.0f, 0);

    // 3. Scores: Q @ K^T (scale+mask+causal fused; above-diagonal blocks skipped)
    mma_gemm<true, 2, true, false, false><<<dim3(16, 16, BH), 256, SMEM>>>(
        q, out_k, scores, nullptr, nullptr, nullptr,
        S_, S_, DH, (size_t)S_ * DH, (size_t)S_ * DH, (size_t)S_ * S_,
        mask, scale, S_);

    // 4. Prefix softmax
    softmax_kernel<<<dim3(S_, BH), 256>>>(scores);

    // 5. ctx: probs @ V, K truncated at diagonal, written merged into out_ctx
    mma_gemm<false, 0, false, true, true><<<dim3(1, 16, BH), 256, SMEM>>>(
        scores, out_v, out_ctx, nullptr, nullptr, nullptr,
        S_, DH, S_, (size_t)S_ * S_, (size_t)S_ * DH, 0,
        nullptr, 1.0f, 0);

    // 6. Output projection
    mma_gemm<false, 0, false, false, false><<<dim3(16, 32, 1), 256, SMEM>>>(
        out_ctx, ow, out_o, nullptr, nullptr, nullptr,
        B_ * S_, H_, H_, 0, 0, 0, nullptr, 1.0f, 0);
}

// round 4
// speedup vs baseline: 4.4213x; 1.0274x over previous
#include <cuda_runtime.h>
#include <cstdint>
#include <math.h>

#define B_    2
#define S_    2048
#define H_    2048
#define HEADS 16
#define DH    128
#define BH    (B_*HEADS)
#define BSH   ((size_t)B_*S_*H_)

// ---------------------------------------------------------------------------
// Scratch
// ---------------------------------------------------------------------------
__device__ float g_q[BSH];   // [B,HEADS,S,DH]

// ---------------------------------------------------------------------------
// Helpers
// ---------------------------------------------------------------------------
__device__ __forceinline__ uint32_t f2tf(float f) {
    uint32_t r;
    asm("cvt.rna.tf32.f32 %0, %1;" : "=r"(r) : "f"(f));
    return r;
}
__device__ __forceinline__ void mma_tf32(float* c, const uint32_t* a, const uint32_t* b) {
    asm volatile(
        "mma.sync.aligned.m16n8k8.row.col.f32.tf32.tf32.f32 "
        "{%0,%1,%2,%3},{%4,%5,%6,%7},{%8,%9},{%0,%1,%2,%3};\n"
        : "+f"(c[0]), "+f"(c[1]), "+f"(c[2]), "+f"(c[3])
        : "r"(a[0]), "r"(a[1]), "r"(a[2]), "r"(a[3]), "r"(b[0]), "r"(b[1]));
}
__device__ __forceinline__ void cp16(uint32_t dst, const float* src) {
    asm volatile("cp.async.cg.shared.global [%0], [%1], 16;\n" :: "r"(dst), "l"(src));
}
#define CP_COMMIT() asm volatile("cp.async.commit_group;\n")
#define CP_WAIT0()  asm volatile("cp.async.wait_group 0;\n")

// ---------------------------------------------------------------------------
// LayerNorm
// ---------------------------------------------------------------------------
__global__ void __launch_bounds__(256) ln_kernel(
    const float* __restrict__ x, const float* __restrict__ g,
    const float* __restrict__ b, float* __restrict__ y)
{
    const size_t row = blockIdx.x;
    const float* xr = x + row * H_;
    float s = 0.f, ss = 0.f;
    for (int i = threadIdx.x; i < H_; i += 256) {
        float t = xr[i];
        s += t; ss += t * t;
    }
    #pragma unroll
    for (int o = 16; o; o >>= 1) {
        s  += __shfl_xor_sync(0xffffffffu, s,  o);
        ss += __shfl_xor_sync(0xffffffffu, ss, o);
    }
    __shared__ float red[2][8];
    const int w = threadIdx.x >> 5, l = threadIdx.x & 31;
    if (l == 0) { red[0][w] = s; red[1][w] = ss; }
    __syncthreads();
    __shared__ float stats[2];
    if (threadIdx.x == 0) {
        float S = 0.f, SS = 0.f;
        #pragma unroll
        for (int i = 0; i < 8; i++) { S += red[0][i]; SS += red[1][i]; }
        float mu  = S / (float)H_;
        float var = SS / (float)H_ - mu * mu;
        stats[0] = mu;
        stats[1] = rsqrtf(var + 1e-12f);
    }
    __syncthreads();
    const float mu = stats[0], rstd = stats[1];
    float* yr = y + row * H_;
    for (int i = threadIdx.x; i < H_; i += 256)
        yr[i] = (xr[i] - mu) * rstd * g[i] + b[i];
}

// ---------------------------------------------------------------------------
// TF32 tensor-core GEMM (NN), 128x128 CTA tile, K-tile 32, 256 threads.
// A staged LDG->cvt->STS (tf32 bits in smem); B via cp.async.
// EPI: 0 plain, 3 qkv-scatter(+bias)
// ---------------------------------------------------------------------------
template<int EPI>
__global__ void __launch_bounds__(256, 2) mma_gemm(
    const float* __restrict__ A, const float* __restrict__ Bm,
    float* __restrict__ C,
    float* __restrict__ Cq, float* __restrict__ Ckk, float* __restrict__ Cv,
    int M, int N, int K, const float* __restrict__ extra)
{
    const int rowBase = blockIdx.y * 128;
    const int colBase = blockIdx.x * 128;

    extern __shared__ uint32_t sm4[];
    uint32_t* A_s = sm4;                                  // [2][128][36] tf32
    float*    B_s = (float*)(sm4 + 2 * 128 * 36);         // [2][32][136]
    const int ASTAGE = 128 * 36;
    const int BSTAGE = 32 * 136;

    const int tx = threadIdx.x;
    const int lane = tx & 31, warp = tx >> 5;
    const int wm = (warp >> 2) * 64;
    const int wn = (warp & 3) * 32;
    const int lr = lane >> 2;
    const int lc = lane & 3;

    const int aRow  = tx >> 3;
    const int aCol4 = (tx & 7) * 4;
    const int bRow  = tx >> 5;
    const int bCol4 = (tx & 31) * 4;

    const uint32_t sBaddr = (uint32_t)__cvta_generic_to_shared(&B_s[bRow * 136 + bCol4]);
    const float* gA0 = A + (size_t)(rowBase + aRow) * K + aCol4;
    const float* gB0 = Bm + (size_t)bRow * N + colBase + bCol4;

    const int ktEnd = K >> 5;

    float acc[4][4][4];
    #pragma unroll
    for (int i = 0; i < 4; i++)
        #pragma unroll
        for (int j = 0; j < 4; j++)
            #pragma unroll
            for (int r = 0; r < 4; r++) acc[i][j][r] = 0.f;

    float4 ra[4];
    auto ldgA = [&](int kt) {
        #pragma unroll
        for (int i = 0; i < 4; i++)
            ra[i] = *(const float4*)(gA0 + kt * 32 + (size_t)i * 32 * K);
    };
    auto stsA = [&](int buf) {
        uint32_t* dst = A_s + buf * ASTAGE + aRow * 36 + aCol4;
        #pragma unroll
        for (int i = 0; i < 4; i++) {
            uint4 u;
            u.x = f2tf(ra[i].x); u.y = f2tf(ra[i].y);
            u.z = f2tf(ra[i].z); u.w = f2tf(ra[i].w);
            *(uint4*)(dst + i * 32 * 36) = u;
        }
    };
    auto cpB = [&](int kt, int buf) {
        uint32_t db = sBaddr + buf * BSTAGE * 4;
        const float* gb = gB0 + (size_t)kt * 32 * N;
        #pragma unroll
        for (int i = 0; i < 4; i++)
            cp16(db + i * 8 * 136 * 4, gb + (size_t)i * 8 * N);
    };

    ldgA(0);
    cpB(0, 0); CP_COMMIT();
    stsA(0);
    CP_WAIT0();
    __syncthreads();

    for (int kt = 0; kt < ktEnd; kt++) {
        const int buf = kt & 1;
        const bool more = (kt + 1 < ktEnd);
        if (more) {
            ldgA(kt + 1);
            cpB(kt + 1, buf ^ 1); CP_COMMIT();
        }

        const uint32_t* As = A_s + buf * ASTAGE;
        const float*    Bs = B_s + buf * BSTAGE;

        #pragma unroll
        for (int ks = 0; ks < 4; ks++) {
            uint32_t af[4][4];
            #pragma unroll
            for (int mt = 0; mt < 4; mt++) {
                const uint32_t* p = As + (wm + mt * 16 + lr) * 36 + ks * 8 + lc;
                af[mt][0] = p[0];
                af[mt][1] = p[8 * 36];
                af[mt][2] = p[4];
                af[mt][3] = p[8 * 36 + 4];
            }
            uint32_t bf[4][2];
            #pragma unroll
            for (int nt = 0; nt < 4; nt++) {
                const float* p = Bs + (ks * 8 + lc) * 136 + wn + nt * 8 + lr;
                bf[nt][0] = f2tf(p[0]);
                bf[nt][1] = f2tf(p[4 * 136]);
            }
            #pragma unroll
            for (int mt = 0; mt < 4; mt++)
                #pragma unroll
                for (int nt = 0; nt < 4; nt++)
                    mma_tf32(acc[mt][nt], af[mt], bf[nt]);
        }

        if (more) {
            stsA(buf ^ 1);
            CP_WAIT0();
            __syncthreads();
        }
    }

    if (EPI == 3) {
        const int whichBlk = colBase >> 11;
        float* base = (whichBlk == 0) ? Cq : (whichBlk == 1) ? Ckk : Cv;
        const int h = (colBase & 2047) >> 7;
        #pragma unroll
        for (int mt = 0; mt < 4; mt++) {
            #pragma unroll
            for (int nt = 0; nt < 4; nt++) {
                const int d  = wn + nt * 8 + 2 * lc;
                const int gn = colBase + d;
                float* a = acc[mt][nt];
                #pragma unroll
                for (int r = 0; r < 2; r++) {
                    const int m = rowBase + wm + mt * 16 + lr + r * 8;
                    const int b = m >> 11, s = m & 2047;
                    float2 o2 = make_float2(a[r * 2 + 0] + extra[gn],
                                            a[r * 2 + 1] + extra[gn + 1]);
                    *(float2*)&base[((((size_t)b * 16 + h) << 11) + s) * 128 + d] = o2;
                }
            }
        }
        return;
    }

    #pragma unroll
    for (int mt = 0; mt < 4; mt++) {
        #pragma unroll
        for (int nt = 0; nt < 4; nt++) {
            const int gm = rowBase + wm + mt * 16 + lr;
            const int gn = colBase + wn + nt * 8 + 2 * lc;
            float* a = acc[mt][nt];
            #pragma unroll
            for (int r = 0; r < 2; r++)
                *(float2*)&C[(size_t)(gm + r * 8) * N + gn] =
                    make_float2(a[r * 2 + 0], a[r * 2 + 1]);
        }
    }
}

// ---------------------------------------------------------------------------
// Flash attention: fused scores + online softmax + probs@V.
// Grid (16 q-tiles, 32 bh), 256 threads (8 warps x 16 rows).
// Q frags in registers; K/V cp.async + in-place tf32 cvt, double buffered;
// P via warp-private smem. Writes ctx merged [B,S,H].
// ---------------------------------------------------------------------------
#define KS_STRIDE 132
#define VS_STRIDE 136
#define K_STAGE   (64*KS_STRIDE)
#define V_STAGE   (64*VS_STRIDE)
#define P_STRIDE  68

__global__ void __launch_bounds__(256, 1) flash_kernel(
    const float* __restrict__ q, const float* __restrict__ k,
    const float* __restrict__ v, const float* __restrict__ mask,
    float* __restrict__ ctx, float scale)
{
    const int qi = gridDim.x - 1 - blockIdx.x;    // heavy tiles first
    const int rowBase = qi * 128;
    const int bh = blockIdx.y;
    const int b = bh >> 4, h = bh & 15;

    const float* Q = q + (size_t)bh * S_ * DH;
    const float* K = k + (size_t)bh * S_ * DH;
    const float* V = v + (size_t)bh * S_ * DH;
    const float* mrow = mask + (size_t)b * S_;

    extern __shared__ uint32_t smf[];
    uint32_t* Ks = smf;                    // [2][64][132]
    uint32_t* Vs = smf + 2 * K_STAGE;      // [2][64][136]
    uint32_t* Ps = Vs + 2 * V_STAGE;       // [8][16][68]

    const int tx = threadIdx.x;
    const int lane = tx & 31, wid = tx >> 5;
    const int lr = lane >> 2, lc = lane & 3;

    const int r0  = wid * 16 + lr;   // local row in q-tile
    const int r0g = rowBase + r0;    // global q row
    const int r1g = r0g + 8;

    // ---- Stage Q through the K region (raw floats, 128x132) ----
    {
        float* qs = (float*)Ks;
        #pragma unroll
        for (int i = 0; i < 16; i++) {
            int e = tx + i * 256;
            int row = e >> 5, c4 = (e & 31) * 4;
            cp16((uint32_t)__cvta_generic_to_shared(qs + row * KS_STRIDE + c4),
                 Q + (size_t)(rowBase + row) * DH + c4);
        }
        CP_COMMIT(); CP_WAIT0();
        __syncthreads();
    }
    uint32_t qf[16][4];
    {
        const float* qs = (const float*)Ks;
        #pragma unroll
        for (int ks = 0; ks < 16; ks++) {
            qf[ks][0] = f2tf(qs[(r0)     * KS_STRIDE + ks * 8 + lc]);
            qf[ks][1] = f2tf(qs[(r0 + 8) * KS_STRIDE + ks * 8 + lc]);
            qf[ks][2] = f2tf(qs[(r0)     * KS_STRIDE + ks * 8 + lc + 4]);
            qf[ks][3] = f2tf(qs[(r0 + 8) * KS_STRIDE + ks * 8 + lc + 4]);
        }
    }
    __syncthreads();

    const int jEnd = 2 * qi + 2;

    auto cpKV = [&](int j, int st) {
        float* kd = (float*)(Ks + st * K_STAGE);
        float* vd = (float*)(Vs + st * V_STAGE);
        const float* ksrc = K + (size_t)j * 64 * DH;
        const float* vsrc = V + (size_t)j * 64 * DH;
        #pragma unroll
        for (int i = 0; i < 8; i++) {
            int e = tx + i * 256;
            int row = e >> 5, c4 = (e & 31) * 4;
            cp16((uint32_t)__cvta_generic_to_shared(kd + row * KS_STRIDE + c4),
                 ksrc + (size_t)row * DH + c4);
            cp16((uint32_t)__cvta_generic_to_shared(vd + row * VS_STRIDE + c4),
                 vsrc + (size_t)row * DH + c4);
        }
    };
    auto cvtKV = [&](int st) {
        uint32_t* kd = Ks + st * K_STAGE;
        uint32_t* vd = Vs + st * V_STAGE;
        #pragma unroll
        for (int i = 0; i < 8; i++) {
            int e = tx + i * 256;
            int row = e >> 5, c4 = (e & 31) * 4;
            float4 kf = *(float4*)(kd + row * KS_STRIDE + c4);
            uint4 ku;
            ku.x = f2tf(kf.x); ku.y = f2tf(kf.y); ku.z = f2tf(kf.z); ku.w = f2tf(kf.w);
            *(uint4*)(kd + row * KS_STRIDE + c4) = ku;
            float4 vf = *(float4*)(vd + row * VS_STRIDE + c4);
            uint4 vu;
            vu.x = f2tf(vf.x); vu.y = f2tf(vf.y); vu.z = f2tf(vf.z); vu.w = f2tf(vf.w);
            *(uint4*)(vd + row * VS_STRIDE + c4) = vu;
        }
    };

    cpKV(0, 0); CP_COMMIT(); CP_WAIT0();
    __syncthreads();
    cvtKV(0);
    __syncthreads();

    float oacc[16][4];
    #pragma unroll
    for (int i = 0; i < 16; i++)
        #pragma unroll
        for (int r = 0; r < 4; r++) oacc[i][r] = 0.f;
    float m0 = -1e30f, m1 = -1e30f, l0 = 0.f, l1 = 0.f;

    uint32_t* pw = Ps + wid * 16 * P_STRIDE;

    for (int j = 0; j < jEnd; j++) {
        const int st = j & 1;
        const bool more = (j + 1 < jEnd);
        if (more) { cpKV(j + 1, st ^ 1); CP_COMMIT(); }

        // ---- S = Q @ K^T over this 64-key tile ----
        float sacc[8][4];
        #pragma unroll
        for (int nt = 0; nt < 8; nt++)
            #pragma unroll
            for (int r = 0; r < 4; r++) sacc[nt][r] = 0.f;

        const uint32_t* kbase = Ks + st * K_STAGE;
        #pragma unroll
        for (int ks = 0; ks < 16; ks++) {
            uint32_t bf[8][2];
            #pragma unroll
            for (int nt = 0; nt < 8; nt++) {
                const uint32_t* p = kbase + (nt * 8 + lr) * KS_STRIDE + ks * 8 + lc;
                bf[nt][0] = p[0];
                bf[nt][1] = p[4];
            }
            #pragma unroll
            for (int nt = 0; nt < 8; nt++)
                mma_tf32(sacc[nt], qf[ks], bf[nt]);
        }

        // ---- scale + mask + causal + online softmax ----
        const int keyBase = j * 64;
        float mt0 = -1e30f, mt1 = -1e30f;
        #pragma unroll
        for (int nt = 0; nt < 8; nt++) {
            const int kcol = keyBase + nt * 8 + 2 * lc;
            float2 mk = *(const float2*)&mrow[kcol];
            float s0 = sacc[nt][0] * scale + mk.x;
            float s1 = sacc[nt][1] * scale + mk.y;
            float s2 = sacc[nt][2] * scale + mk.x;
            float s3 = sacc[nt][3] * scale + mk.y;
            if (kcol     > r0g) s0 = -10000.f;
            if (kcol + 1 > r0g) s1 = -10000.f;
            if (kcol     > r1g) s2 = -10000.f;
            if (kcol + 1 > r1g) s3 = -10000.f;
            sacc[nt][0] = s0; sacc[nt][1] = s1; sacc[nt][2] = s2; sacc[nt][3] = s3;
            mt0 = fmaxf(mt0, fmaxf(s0, s1));
            mt1 = fmaxf(mt1, fmaxf(s2, s3));
        }
        mt0 = fmaxf(mt0, __shfl_xor_sync(0xffffffffu, mt0, 1));
        mt0 = fmaxf(mt0, __shfl_xor_sync(0xffffffffu, mt0, 2));
        mt1 = fmaxf(mt1, __shfl_xor_sync(0xffffffffu, mt1, 1));
        mt1 = fmaxf(mt1, __shfl_xor_sync(0xffffffffu, mt1, 2));

        const float mn0 = fmaxf(m0, mt0), mn1 = fmaxf(m1, mt1);
        const float a0 = __expf(m0 - mn0), a1 = __expf(m1 - mn1);
        m0 = mn0; m1 = mn1;

        float ts0 = 0.f, ts1 = 0.f;
        #pragma unroll
        for (int nt = 0; nt < 8; nt++) {
            float p0 = __expf(sacc[nt][0] - mn0);
            float p1 = __expf(sacc[nt][1] - mn0);
            float p2 = __expf(sacc[nt][2] - mn1);
            float p3 = __expf(sacc[nt][3] - mn1);
            sacc[nt][0] = p0; sacc[nt][1] = p1; sacc[nt][2] = p2; sacc[nt][3] = p3;
            ts0 += p0 + p1;
            ts1 += p2 + p3;
        }
        ts0 += __shfl_xor_sync(0xffffffffu, ts0, 1);
        ts0 += __shfl_xor_sync(0xffffffffu, ts0, 2);
        ts1 += __shfl_xor_sync(0xffffffffu, ts1, 1);
        ts1 += __shfl_xor_sync(0xffffffffu, ts1, 2);
        l0 = l0 * a0 + ts0;
        l1 = l1 * a1 + ts1;

        #pragma unroll
        for (int nt = 0; nt < 16; nt++) {
            oacc[nt][0] *= a0; oacc[nt][1] *= a0;
            oacc[nt][2] *= a1; oacc[nt][3] *= a1;
        }

        // ---- P -> warp-private smem (tf32) ----
        __syncwarp();
        #pragma unroll
        for (int nt = 0; nt < 8; nt++) {
            uint2 u0 = make_uint2(f2tf(sacc[nt][0]), f2tf(sacc[nt][1]));
            uint2 u1 = make_uint2(f2tf(sacc[nt][2]), f2tf(sacc[nt][3]));
            *(uint2*)(pw + (lr)     * P_STRIDE + nt * 8 + 2 * lc) = u0;
            *(uint2*)(pw + (lr + 8) * P_STRIDE + nt * 8 + 2 * lc) = u1;
        }
        __syncwarp();

        // ---- O += P @ V ----
        const uint32_t* vbase = Vs + st * V_STAGE;
        #pragma unroll
        for (int ks = 0; ks < 8; ks++) {
            uint32_t af[4];
            af[0] = pw[(lr)     * P_STRIDE + ks * 8 + lc];
            af[1] = pw[(lr + 8) * P_STRIDE + ks * 8 + lc];
            af[2] = pw[(lr)     * P_STRIDE + ks * 8 + lc + 4];
            af[3] = pw[(lr + 8) * P_STRIDE + ks * 8 + lc + 4];
            #pragma unroll
            for (int nt = 0; nt < 16; nt++) {
                const uint32_t* p = vbase + (ks * 8 + lc) * VS_STRIDE + nt * 8 + lr;
                uint32_t bf2[2] = { p[0], p[4 * VS_STRIDE] };
                mma_tf32(oacc[nt], af, bf2);
            }
        }

        if (more) {
            CP_WAIT0();
            __syncthreads();
            cvtKV(st ^ 1);
            __syncthreads();
        }
    }

    // ---- epilogue: normalize and write merged ctx [B,S,H] ----
    const float inv0 = 1.0f / l0;
    const float inv1 = 1.0f / l1;
    float* c0 = ctx + ((size_t)b * S_ + r0g) * H_ + h * 128 + 2 * lc;
    float* c1 = ctx + ((size_t)b * S_ + r1g) * H_ + h * 128 + 2 * lc;
    #pragma unroll
    for (int nt = 0; nt < 16; nt++) {
        *(float2*)(c0 + nt * 8) = make_float2(oacc[nt][0] * inv0, oacc[nt][1] * inv0);
        *(float2*)(c1 + nt * 8) = make_float2(oacc[nt][2] * inv1, oacc[nt][3] * inv1);
    }
}

// ---------------------------------------------------------------------------
// kernel_launch
// ---------------------------------------------------------------------------
extern "C" void kernel_launch(void* const* d_in, const int* in_sizes, int n_in,
                              void* d_out, int out_size)
{
    const float* x    = (const float*)d_in[0];
    const float* mask = (const float*)d_in[1];
    const float* qkvw = (const float*)d_in[2];
    const float* qkvb = (const float*)d_in[3];
    const float* ow   = (const float*)d_in[4];
    const float* nw   = (const float*)d_in[5];
    const float* nb   = (const float*)d_in[6];

    float* out     = (float*)d_out;
    float* out_o   = out;
    float* out_k   = out + 1 * BSH;
    float* out_v   = out + 2 * BSH;
    float* out_ctx = out + 3 * BSH;
    float* out_ln  = out + 4 * BSH;

    float* q;
    cudaGetSymbolAddress((void**)&q, g_q);

    const int GEMM_SMEM  = (2 * 128 * 36 + 2 * 32 * 136) * 4;                     // 71680 B
    const int FLASH_SMEM = (2 * K_STAGE + 2 * V_STAGE + 8 * 16 * P_STRIDE) * 4;   // 172032 B

    cudaFuncSetAttribute(mma_gemm<3>, cudaFuncAttributeMaxDynamicSharedMemorySize, GEMM_SMEM);
    cudaFuncSetAttribute(mma_gemm<0>, cudaFuncAttributeMaxDynamicSharedMemorySize, GEMM_SMEM);
    cudaFuncSetAttribute(flash_kernel, cudaFuncAttributeMaxDynamicSharedMemorySize, FLASH_SMEM);

    const float scale = 1.0f / sqrtf((float)DH);

    // 1. LayerNorm -> out_ln
    ln_kernel<<<B_ * S_, 256>>>(x, nw, nb, out_ln);

    // 2. QKV GEMM + bias, scattering q->g_q, k->out_k, v->out_v in [B,H,S,dh]
    mma_gemm<3><<<dim3(48, 32, 1), 256, GEMM_SMEM>>>(
        out_ln, qkvw, nullptr, q, out_k, out_v, B_ * S_, 3 * H_, H_, qkvb);

    // 3. Fused flash attention -> out_ctx (merged [B,S,H])
    flash_kernel<<<dim3(16, BH), 256, FLASH_SMEM>>>(
        q, out_k, out_v, mask, out_ctx, scale);

    // 4. Output projection
    mma_gemm<0><<<dim3(16, 32, 1), 256, GEMM_SMEM>>>(
        out_ctx, ow, out_o, nullptr, nullptr, nullptr, B_ * S_, H_, H_, nullptr);
}

// round 5
// speedup vs baseline: 4.4284x; 1.0016x over previous
#include <cuda_runtime.h>
#include <cstdint>
#include <math.h>

#define B_    2
#define S_    2048
#define H_    2048
#define HEADS 16
#define DH    128
#define BH    (B_*HEADS)
#define BSH   ((size_t)B_*S_*H_)

// ---------------------------------------------------------------------------
// Scratch
// ---------------------------------------------------------------------------
__device__ float g_q[BSH];   // [B,HEADS,S,DH]

// ---------------------------------------------------------------------------
// Helpers
// ---------------------------------------------------------------------------
__device__ __forceinline__ uint32_t f2tf(float f) {
    uint32_t r;
    asm("cvt.rna.tf32.f32 %0, %1;" : "=r"(r) : "f"(f));
    return r;
}
__device__ __forceinline__ void mma_tf32(float* c, const uint32_t* a, const uint32_t* b) {
    asm volatile(
        "mma.sync.aligned.m16n8k8.row.col.f32.tf32.tf32.f32 "
        "{%0,%1,%2,%3},{%4,%5,%6,%7},{%8,%9},{%0,%1,%2,%3};\n"
        : "+f"(c[0]), "+f"(c[1]), "+f"(c[2]), "+f"(c[3])
        : "r"(a[0]), "r"(a[1]), "r"(a[2]), "r"(a[3]), "r"(b[0]), "r"(b[1]));
}
__device__ __forceinline__ void cp16(uint32_t dst, const float* src) {
    asm volatile("cp.async.cg.shared.global [%0], [%1], 16;\n" :: "r"(dst), "l"(src));
}
#define CP_COMMIT() asm volatile("cp.async.commit_group;\n")
#define CP_WAIT0()  asm volatile("cp.async.wait_group 0;\n")

// ---------------------------------------------------------------------------
// LayerNorm
// ---------------------------------------------------------------------------
__global__ void __launch_bounds__(256) ln_kernel(
    const float* __restrict__ x, const float* __restrict__ g,
    const float* __restrict__ b, float* __restrict__ y)
{
    const size_t row = blockIdx.x;
    const float* xr = x + row * H_;
    float s = 0.f, ss = 0.f;
    for (int i = threadIdx.x; i < H_; i += 256) {
        float t = xr[i];
        s += t; ss += t * t;
    }
    #pragma unroll
    for (int o = 16; o; o >>= 1) {
        s  += __shfl_xor_sync(0xffffffffu, s,  o);
        ss += __shfl_xor_sync(0xffffffffu, ss, o);
    }
    __shared__ float red[2][8];
    const int w = threadIdx.x >> 5, l = threadIdx.x & 31;
    if (l == 0) { red[0][w] = s; red[1][w] = ss; }
    __syncthreads();
    __shared__ float stats[2];
    if (threadIdx.x == 0) {
        float S = 0.f, SS = 0.f;
        #pragma unroll
        for (int i = 0; i < 8; i++) { S += red[0][i]; SS += red[1][i]; }
        float mu  = S / (float)H_;
        float var = SS / (float)H_ - mu * mu;
        stats[0] = mu;
        stats[1] = rsqrtf(var + 1e-12f);
    }
    __syncthreads();
    const float mu = stats[0], rstd = stats[1];
    float* yr = y + row * H_;
    for (int i = threadIdx.x; i < H_; i += 256)
        yr[i] = (xr[i] - mu) * rstd * g[i] + b[i];
}

// ---------------------------------------------------------------------------
// TF32 tensor-core GEMM (NN), 128x128 CTA tile, K-tile 32, 256 threads.
// A staged LDG->cvt->STS (tf32 bits in smem); B via cp.async.
// EPI: 0 plain, 3 qkv-scatter(+bias)
// ---------------------------------------------------------------------------
template<int EPI>
__global__ void __launch_bounds__(256, 2) mma_gemm(
    const float* __restrict__ A, const float* __restrict__ Bm,
    float* __restrict__ C,
    float* __restrict__ Cq, float* __restrict__ Ckk, float* __restrict__ Cv,
    int M, int N, int K, const float* __restrict__ extra)
{
    const int rowBase = blockIdx.y * 128;
    const int colBase = blockIdx.x * 128;

    extern __shared__ uint32_t sm4[];
    uint32_t* A_s = sm4;                                  // [2][128][36] tf32
    float*    B_s = (float*)(sm4 + 2 * 128 * 36);         // [2][32][136]
    const int ASTAGE = 128 * 36;
    const int BSTAGE = 32 * 136;

    const int tx = threadIdx.x;
    const int lane = tx & 31, warp = tx >> 5;
    const int wm = (warp >> 2) * 64;
    const int wn = (warp & 3) * 32;
    const int lr = lane >> 2;
    const int lc = lane & 3;

    const int aRow  = tx >> 3;
    const int aCol4 = (tx & 7) * 4;
    const int bRow  = tx >> 5;
    const int bCol4 = (tx & 31) * 4;

    const uint32_t sBaddr = (uint32_t)__cvta_generic_to_shared(&B_s[bRow * 136 + bCol4]);
    const float* gA0 = A + (size_t)(rowBase + aRow) * K + aCol4;
    const float* gB0 = Bm + (size_t)bRow * N + colBase + bCol4;

    const int ktEnd = K >> 5;

    float acc[4][4][4];
    #pragma unroll
    for (int i = 0; i < 4; i++)
        #pragma unroll
        for (int j = 0; j < 4; j++)
            #pragma unroll
            for (int r = 0; r < 4; r++) acc[i][j][r] = 0.f;

    float4 ra[4];
    auto ldgA = [&](int kt) {
        #pragma unroll
        for (int i = 0; i < 4; i++)
            ra[i] = *(const float4*)(gA0 + kt * 32 + (size_t)i * 32 * K);
    };
    auto stsA = [&](int buf) {
        uint32_t* dst = A_s + buf * ASTAGE + aRow * 36 + aCol4;
        #pragma unroll
        for (int i = 0; i < 4; i++) {
            uint4 u;
            u.x = f2tf(ra[i].x); u.y = f2tf(ra[i].y);
            u.z = f2tf(ra[i].z); u.w = f2tf(ra[i].w);
            *(uint4*)(dst + i * 32 * 36) = u;
        }
    };
    auto cpB = [&](int kt, int buf) {
        uint32_t db = sBaddr + buf * BSTAGE * 4;
        const float* gb = gB0 + (size_t)kt * 32 * N;
        #pragma unroll
        for (int i = 0; i < 4; i++)
            cp16(db + i * 8 * 136 * 4, gb + (size_t)i * 8 * N);
    };

    ldgA(0);
    cpB(0, 0); CP_COMMIT();
    stsA(0);
    CP_WAIT0();
    __syncthreads();

    for (int kt = 0; kt < ktEnd; kt++) {
        const int buf = kt & 1;
        const bool more = (kt + 1 < ktEnd);
        if (more) {
            ldgA(kt + 1);
            cpB(kt + 1, buf ^ 1); CP_COMMIT();
        }

        const uint32_t* As = A_s + buf * ASTAGE;
        const float*    Bs = B_s + buf * BSTAGE;

        #pragma unroll
        for (int ks = 0; ks < 4; ks++) {
            uint32_t af[4][4];
            #pragma unroll
            for (int mt = 0; mt < 4; mt++) {
                const uint32_t* p = As + (wm + mt * 16 + lr) * 36 + ks * 8 + lc;
                af[mt][0] = p[0];
                af[mt][1] = p[8 * 36];
                af[mt][2] = p[4];
                af[mt][3] = p[8 * 36 + 4];
            }
            uint32_t bf[4][2];
            #pragma unroll
            for (int nt = 0; nt < 4; nt++) {
                const float* p = Bs + (ks * 8 + lc) * 136 + wn + nt * 8 + lr;
                bf[nt][0] = f2tf(p[0]);
                bf[nt][1] = f2tf(p[4 * 136]);
            }
            #pragma unroll
            for (int mt = 0; mt < 4; mt++)
                #pragma unroll
                for (int nt = 0; nt < 4; nt++)
                    mma_tf32(acc[mt][nt], af[mt], bf[nt]);
        }

        if (more) {
            stsA(buf ^ 1);
            CP_WAIT0();
            __syncthreads();
        }
    }

    if (EPI == 3) {
        const int whichBlk = colBase >> 11;
        float* base = (whichBlk == 0) ? Cq : (whichBlk == 1) ? Ckk : Cv;
        const int h = (colBase & 2047) >> 7;
        #pragma unroll
        for (int mt = 0; mt < 4; mt++) {
            #pragma unroll
            for (int nt = 0; nt < 4; nt++) {
                const int d  = wn + nt * 8 + 2 * lc;
                const int gn = colBase + d;
                float* a = acc[mt][nt];
                #pragma unroll
                for (int r = 0; r < 2; r++) {
                    const int m = rowBase + wm + mt * 16 + lr + r * 8;
                    const int b = m >> 11, s = m & 2047;
                    float2 o2 = make_float2(a[r * 2 + 0] + extra[gn],
                                            a[r * 2 + 1] + extra[gn + 1]);
                    *(float2*)&base[((((size_t)b * 16 + h) << 11) + s) * 128 + d] = o2;
                }
            }
        }
        return;
    }

    #pragma unroll
    for (int mt = 0; mt < 4; mt++) {
        #pragma unroll
        for (int nt = 0; nt < 4; nt++) {
            const int gm = rowBase + wm + mt * 16 + lr;
            const int gn = colBase + wn + nt * 8 + 2 * lc;
            float* a = acc[mt][nt];
            #pragma unroll
            for (int r = 0; r < 2; r++)
                *(float2*)&C[(size_t)(gm + r * 8) * N + gn] =
                    make_float2(a[r * 2 + 0], a[r * 2 + 1]);
        }
    }
}

// ---------------------------------------------------------------------------
// Flash attention: fused scores + online softmax + probs@V.
// Grid (16 q-tiles, 32 bh), 256 threads (8 warps x 16 rows).
// Q frags in registers; K/V cp.async + in-place tf32 cvt, double buffered;
// P via warp-private smem. Writes ctx merged [B,S,H].
// ---------------------------------------------------------------------------
#define KS_STRIDE 132
#define VS_STRIDE 136
#define K_STAGE   (64*KS_STRIDE)
#define V_STAGE   (64*VS_STRIDE)
#define P_STRIDE  68

__global__ void __launch_bounds__(256, 1) flash_kernel(
    const float* __restrict__ q, const float* __restrict__ k,
    const float* __restrict__ v, const float* __restrict__ mask,
    float* __restrict__ ctx, float scale)
{
    const int qi = gridDim.x - 1 - blockIdx.x;    // heavy tiles first
    const int rowBase = qi * 128;
    const int bh = blockIdx.y;
    const int b = bh >> 4, h = bh & 15;

    const float* Q = q + (size_t)bh * S_ * DH;
    const float* K = k + (size_t)bh * S_ * DH;
    const float* V = v + (size_t)bh * S_ * DH;
    const float* mrow = mask + (size_t)b * S_;

    extern __shared__ uint32_t smf[];
    uint32_t* Ks = smf;                    // [2][64][132]
    uint32_t* Vs = smf + 2 * K_STAGE;      // [2][64][136]
    uint32_t* Ps = Vs + 2 * V_STAGE;       // [8][16][68]

    const int tx = threadIdx.x;
    const int lane = tx & 31, wid = tx >> 5;
    const int lr = lane >> 2, lc = lane & 3;

    const int r0  = wid * 16 + lr;   // local row in q-tile
    const int r0g = rowBase + r0;    // global q row
    const int r1g = r0g + 8;

    // ---- Stage Q through the K region (raw floats, 128x132) ----
    {
        float* qs = (float*)Ks;
        #pragma unroll
        for (int i = 0; i < 16; i++) {
            int e = tx + i * 256;
            int row = e >> 5, c4 = (e & 31) * 4;
            cp16((uint32_t)__cvta_generic_to_shared(qs + row * KS_STRIDE + c4),
                 Q + (size_t)(rowBase + row) * DH + c4);
        }
        CP_COMMIT(); CP_WAIT0();
        __syncthreads();
    }
    uint32_t qf[16][4];
    {
        const float* qs = (const float*)Ks;
        #pragma unroll
        for (int ks = 0; ks < 16; ks++) {
            qf[ks][0] = f2tf(qs[(r0)     * KS_STRIDE + ks * 8 + lc]);
            qf[ks][1] = f2tf(qs[(r0 + 8) * KS_STRIDE + ks * 8 + lc]);
            qf[ks][2] = f2tf(qs[(r0)     * KS_STRIDE + ks * 8 + lc + 4]);
            qf[ks][3] = f2tf(qs[(r0 + 8) * KS_STRIDE + ks * 8 + lc + 4]);
        }
    }
    __syncthreads();

    const int jEnd = 2 * qi + 2;

    auto cpKV = [&](int j, int st) {
        float* kd = (float*)(Ks + st * K_STAGE);
        float* vd = (float*)(Vs + st * V_STAGE);
        const float* ksrc = K + (size_t)j * 64 * DH;
        const float* vsrc = V + (size_t)j * 64 * DH;
        #pragma unroll
        for (int i = 0; i < 8; i++) {
            int e = tx + i * 256;
            int row = e >> 5, c4 = (e & 31) * 4;
            cp16((uint32_t)__cvta_generic_to_shared(kd + row * KS_STRIDE + c4),
                 ksrc + (size_t)row * DH + c4);
            cp16((uint32_t)__cvta_generic_to_shared(vd + row * VS_STRIDE + c4),
                 vsrc + (size_t)row * DH + c4);
        }
    };
    auto cvtKV = [&](int st) {
        uint32_t* kd = Ks + st * K_STAGE;
        uint32_t* vd = Vs + st * V_STAGE;
        #pragma unroll
        for (int i = 0; i < 8; i++) {
            int e = tx + i * 256;
            int row = e >> 5, c4 = (e & 31) * 4;
            float4 kf = *(float4*)(kd + row * KS_STRIDE + c4);
            uint4 ku;
            ku.x = f2tf(kf.x); ku.y = f2tf(kf.y); ku.z = f2tf(kf.z); ku.w = f2tf(kf.w);
            *(uint4*)(kd + row * KS_STRIDE + c4) = ku;
            float4 vf = *(float4*)(vd + row * VS_STRIDE + c4);
            uint4 vu;
            vu.x = f2tf(vf.x); vu.y = f2tf(vf.y); vu.z = f2tf(vf.z); vu.w = f2tf(vf.w);
            *(uint4*)(vd + row * VS_STRIDE + c4) = vu;
        }
    };

    cpKV(0, 0); CP_COMMIT(); CP_WAIT0();
    __syncthreads();
    cvtKV(0);
    __syncthreads();

    float oacc[16][4];
    #pragma unroll
    for (int i = 0; i < 16; i++)
        #pragma unroll
        for (int r = 0; r < 4; r++) oacc[i][r] = 0.f;
    float m0 = -1e30f, m1 = -1e30f, l0 = 0.f, l1 = 0.f;

    uint32_t* pw = Ps + wid * 16 * P_STRIDE;

    for (int j = 0; j < jEnd; j++) {
        const int st = j & 1;
        const bool more = (j + 1 < jEnd);
        if (more) { cpKV(j + 1, st ^ 1); CP_COMMIT(); }

        // ---- S = Q @ K^T over this 64-key tile ----
        float sacc[8][4];
        #pragma unroll
        for (int nt = 0; nt < 8; nt++)
            #pragma unroll
            for (int r = 0; r < 4; r++) sacc[nt][r] = 0.f;

        const uint32_t* kbase = Ks + st * K_STAGE;
        #pragma unroll
        for (int ks = 0; ks < 16; ks++) {
            uint32_t bf[8][2];
            #pragma unroll
            for (int nt = 0; nt < 8; nt++) {
                const uint32_t* p = kbase + (nt * 8 + lr) * KS_STRIDE + ks * 8 + lc;
                bf[nt][0] = p[0];
                bf[nt][1] = p[4];
            }
            #pragma unroll
            for (int nt = 0; nt < 8; nt++)
                mma_tf32(sacc[nt], qf[ks], bf[nt]);
        }

        // ---- scale + mask + causal + online softmax ----
        const int keyBase = j * 64;
        float mt0 = -1e30f, mt1 = -1e30f;
        #pragma unroll
        for (int nt = 0; nt < 8; nt++) {
            const int kcol = keyBase + nt * 8 + 2 * lc;
            float2 mk = *(const float2*)&mrow[kcol];
            float s0 = sacc[nt][0] * scale + mk.x;
            float s1 = sacc[nt][1] * scale + mk.y;
            float s2 = sacc[nt][2] * scale + mk.x;
            float s3 = sacc[nt][3] * scale + mk.y;
            if (kcol     > r0g) s0 = -10000.f;
            if (kcol + 1 > r0g) s1 = -10000.f;
            if (kcol     > r1g) s2 = -10000.f;
            if (kcol + 1 > r1g) s3 = -10000.f;
            sacc[nt][0] = s0; sacc[nt][1] = s1; sacc[nt][2] = s2; sacc[nt][3] = s3;
            mt0 = fmaxf(mt0, fmaxf(s0, s1));
            mt1 = fmaxf(mt1, fmaxf(s2, s3));
        }
        mt0 = fmaxf(mt0, __shfl_xor_sync(0xffffffffu, mt0, 1));
        mt0 = fmaxf(mt0, __shfl_xor_sync(0xffffffffu, mt0, 2));
        mt1 = fmaxf(mt1, __shfl_xor_sync(0xffffffffu, mt1, 1));
        mt1 = fmaxf(mt1, __shfl_xor_sync(0xffffffffu, mt1, 2));

        const float mn0 = fmaxf(m0, mt0), mn1 = fmaxf(m1, mt1);
        const float a0 = __expf(m0 - mn0), a1 = __expf(m1 - mn1);
        m0 = mn0; m1 = mn1;

        float ts0 = 0.f, ts1 = 0.f;
        #pragma unroll
        for (int nt = 0; nt < 8; nt++) {
            float p0 = __expf(sacc[nt][0] - mn0);
            float p1 = __expf(sacc[nt][1] - mn0);
            float p2 = __expf(sacc[nt][2] - mn1);
            float p3 = __expf(sacc[nt][3] - mn1);
            sacc[nt][0] = p0; sacc[nt][1] = p1; sacc[nt][2] = p2; sacc[nt][3] = p3;
            ts0 += p0 + p1;
            ts1 += p2 + p3;
        }
        ts0 += __shfl_xor_sync(0xffffffffu, ts0, 1);
        ts0 += __shfl_xor_sync(0xffffffffu, ts0, 2);
        ts1 += __shfl_xor_sync(0xffffffffu, ts1, 1);
        ts1 += __shfl_xor_sync(0xffffffffu, ts1, 2);
        l0 = l0 * a0 + ts0;
        l1 = l1 * a1 + ts1;

        #pragma unroll
        for (int nt = 0; nt < 16; nt++) {
            oacc[nt][0] *= a0; oacc[nt][1] *= a0;
            oacc[nt][2] *= a1; oacc[nt][3] *= a1;
        }

        // ---- P -> warp-private smem (tf32) ----
        __syncwarp();
        #pragma unroll
        for (int nt = 0; nt < 8; nt++) {
            uint2 u0 = make_uint2(f2tf(sacc[nt][0]), f2tf(sacc[nt][1]));
            uint2 u1 = make_uint2(f2tf(sacc[nt][2]), f2tf(sacc[nt][3]));
            *(uint2*)(pw + (lr)     * P_STRIDE + nt * 8 + 2 * lc) = u0;
            *(uint2*)(pw + (lr + 8) * P_STRIDE + nt * 8 + 2 * lc) = u1;
        }
        __syncwarp();

        // ---- O += P @ V ----
        const uint32_t* vbase = Vs + st * V_STAGE;
        #pragma unroll
        for (int ks = 0; ks < 8; ks++) {
            uint32_t af[4];
            af[0] = pw[(lr)     * P_STRIDE + ks * 8 + lc];
            af[1] = pw[(lr + 8) * P_STRIDE + ks * 8 + lc];
            af[2] = pw[(lr)     * P_STRIDE + ks * 8 + lc + 4];
            af[3] = pw[(lr + 8) * P_STRIDE + ks * 8 + lc + 4];
            #pragma unroll
            for (int nt = 0; nt < 16; nt++) {
                const uint32_t* p = vbase + (ks * 8 + lc) * VS_STRIDE + nt * 8 + lr;
                uint32_t bf2[2] = { p[0], p[4 * VS_STRIDE] };
                mma_tf32(oacc[nt], af, bf2);
            }
        }

        if (more) {
            CP_WAIT0();
            __syncthreads();
            cvtKV(st ^ 1);
            __syncthreads();
        }
    }

    // ---- epilogue: normalize and write merged ctx [B,S,H] ----
    const float inv0 = 1.0f / l0;
    const float inv1 = 1.0f / l1;
    float* c0 = ctx + ((size_t)b * S_ + r0g) * H_ + h * 128 + 2 * lc;
    float* c1 = ctx + ((size_t)b * S_ + r1g) * H_ + h * 128 + 2 * lc;
    #pragma unroll
    for (int nt = 0; nt < 16; nt++) {
        *(float2*)(c0 + nt * 8) = make_float2(oacc[nt][0] * inv0, oacc[nt][1] * inv0);
        *(float2*)(c1 + nt * 8) = make_float2(oacc[nt][2] * inv1, oacc[nt][3] * inv1);
    }
}

// ---------------------------------------------------------------------------
// kernel_launch
// ---------------------------------------------------------------------------
extern "C" void kernel_launch(void* const* d_in, const int* in_sizes, int n_in,
                              void* d_out, int out_size)
{
    const float* x    = (const float*)d_in[0];
    const float* mask = (const float*)d_in[1];
    const float* qkvw = (const float*)d_in[2];
    const float* qkvb = (const float*)d_in[3];
    const float* ow   = (const float*)d_in[4];
    const float* nw   = (const float*)d_in[5];
    const float* nb   = (const float*)d_in[6];

    float* out     = (float*)d_out;
    float* out_o   = out;
    float* out_k   = out + 1 * BSH;
    float* out_v   = out + 2 * BSH;
    float* out_ctx = out + 3 * BSH;
    float* out_ln  = out + 4 * BSH;

    float* q;
    cudaGetSymbolAddress((void**)&q, g_q);

    const int GEMM_SMEM  = (2 * 128 * 36 + 2 * 32 * 136) * 4;                     // 71680 B
    const int FLASH_SMEM = (2 * K_STAGE + 2 * V_STAGE + 8 * 16 * P_STRIDE) * 4;   // 172032 B

    cudaFuncSetAttribute(mma_gemm<3>, cudaFuncAttributeMaxDynamicSharedMemorySize, GEMM_SMEM);
    cudaFuncSetAttribute(mma_gemm<0>, cudaFuncAttributeMaxDynamicSharedMemorySize, GEMM_SMEM);
    cudaFuncSetAttribute(flash_kernel, cudaFuncAttributeMaxDynamicSharedMemorySize, FLASH_SMEM);

    const float scale = 1.0f / sqrtf((float)DH);

    // 1. LayerNorm -> out_ln
    ln_kernel<<<B_ * S_, 256>>>(x, nw, nb, out_ln);

    // 2. QKV GEMM + bias, scattering q->g_q, k->out_k, v->out_v in [B,H,S,dh]
    mma_gemm<3><<<dim3(48, 32, 1), 256, GEMM_SMEM>>>(
        out_ln, qkvw, nullptr, q, out_k, out_v, B_ * S_, 3 * H_, H_, qkvb);

    // 3. Fused flash attention -> out_ctx (merged [B,S,H])
    flash_kernel<<<dim3(16, BH), 256, FLASH_SMEM>>>(
        q, out_k, out_v, mask, out_ctx, scale);

    // 4. Output projection
    mma_gemm<0><<<dim3(16, 32, 1), 256, GEMM_SMEM>>>(
        out_ctx, ow, out_o, nullptr, nullptr, nullptr, B_ * S_, H_, H_, nullptr);
}

// round 7
// speedup vs baseline: 4.6627x; 1.0529x over previous
#include <cuda_runtime.h>
#include <cstdint>
#include <math.h>

#define B_    2
#define S_    2048
#define H_    2048
#define HEADS 16
#define DH    128
#define BH    (B_*HEADS)
#define BSH   ((size_t)B_*S_*H_)
#define KT_A  64            // K=2048 / 32

// ---------------------------------------------------------------------------
// Scratch
// ---------------------------------------------------------------------------
__device__ float g_q[BSH];                      // [B,HEADS,S,DH]
__device__ float g_lnp[BSH];                    // LN output, fragment-major, rounded
__device__ float g_ctxp[BSH];                   // ctx, fragment-major, rounded
__device__ float g_qkvwP[(size_t)3*H_*H_];      // qkvw, B-fragment-major, rounded
__device__ float g_owP[(size_t)H_*H_];          // ow,   B-fragment-major, rounded

// ---------------------------------------------------------------------------
// Helpers
// ---------------------------------------------------------------------------
__device__ __forceinline__ uint32_t f2tf(float f) {
    uint32_t r;
    asm("cvt.rna.tf32.f32 %0, %1;" : "=r"(r) : "f"(f));
    return r;
}
__device__ __forceinline__ void mma_tf32(float* c, const uint32_t* a, const uint32_t* b) {
    asm volatile(
        "mma.sync.aligned.m16n8k8.row.col.f32.tf32.tf32.f32 "
        "{%0,%1,%2,%3},{%4,%5,%6,%7},{%8,%9},{%0,%1,%2,%3};\n"
        : "+f"(c[0]), "+f"(c[1]), "+f"(c[2]), "+f"(c[3])
        : "r"(a[0]), "r"(a[1]), "r"(a[2]), "r"(a[3]), "r"(b[0]), "r"(b[1]));
}
__device__ __forceinline__ void cp16(uint32_t dst, const float* src) {
    asm volatile("cp.async.cg.shared.global [%0], [%1], 16;\n" :: "r"(dst), "l"(src));
}
#define CP_COMMIT() asm volatile("cp.async.commit_group;\n")
#define CP_WAIT0()  asm volatile("cp.async.wait_group 0;\n")
#define CP_WAIT1()  asm volatile("cp.async.wait_group 1;\n")

// A-operand fragment-major index for element (m, k), K=2048:
// [m16][kt][ks][kh][lane=lr*4+lc][rh]
__device__ __forceinline__ size_t permA(int m, int k) {
    return ((size_t)((m >> 4) * KT_A + (k >> 5))) * 512
         + ((((k >> 3) & 3) * 2 + ((k >> 2) & 1)) * 64)
         + (((m & 7) << 2) + (k & 3)) * 2
         + ((m >> 3) & 1);
}

// ---------------------------------------------------------------------------
// Weight prep: w[K=2048][N] -> B-fragment-major per (n32, kt) chunk:
// [n32][kt][ks][kh][laneB=lr*4+lc][nt]  (1024 floats per chunk), tf32-rounded
// ---------------------------------------------------------------------------
__global__ void __launch_bounds__(256) prep_b(
    const float* __restrict__ w, float* __restrict__ out, int N)
{
    const int kt  = blockIdx.x;
    const int n32 = blockIdx.y;
    __shared__ float sm[32][33];
    const int tx = threadIdx.x;
    const int kl = tx >> 5, nl = tx & 31;
    #pragma unroll
    for (int i = 0; i < 32; i += 8)
        sm[kl + i][nl] = w[(size_t)(kt * 32 + kl + i) * N + n32 * 32 + nl];
    __syncthreads();
    const int laneB = tx & 31, ksh = tx >> 5;      // ksh = ks*2+kh
    const int lr = laneB >> 2, lc = laneB & 3;
    const int k_l = (ksh >> 1) * 8 + (ksh & 1) * 4 + lc;
    float4 v;
    v.x = __uint_as_float(f2tf(sm[k_l][lr]));
    v.y = __uint_as_float(f2tf(sm[k_l][8 + lr]));
    v.z = __uint_as_float(f2tf(sm[k_l][16 + lr]));
    v.w = __uint_as_float(f2tf(sm[k_l][24 + lr]));
    *(float4*)&out[((size_t)n32 * KT_A + kt) * 1024 + ksh * 128 + laneB * 4] = v;
}

// ---------------------------------------------------------------------------
// LayerNorm: writes exact y (output) + fragment-major rounded copy
// ---------------------------------------------------------------------------
__global__ void __launch_bounds__(256) ln_kernel(
    const float* __restrict__ x, const float* __restrict__ g,
    const float* __restrict__ b, float* __restrict__ y, float* __restrict__ yp)
{
    const int row = blockIdx.x;
    const float* xr = x + (size_t)row * H_;
    float s = 0.f, ss = 0.f;
    for (int i = threadIdx.x; i < H_; i += 256) {
        float t = xr[i];
        s += t; ss += t * t;
    }
    #pragma unroll
    for (int o = 16; o; o >>= 1) {
        s  += __shfl_xor_sync(0xffffffffu, s,  o);
        ss += __shfl_xor_sync(0xffffffffu, ss, o);
    }
    __shared__ float red[2][8];
    const int w = threadIdx.x >> 5, l = threadIdx.x & 31;
    if (l == 0) { red[0][w] = s; red[1][w] = ss; }
    __syncthreads();
    __shared__ float stats[2];
    if (threadIdx.x == 0) {
        float S = 0.f, SS = 0.f;
        #pragma unroll
        for (int i = 0; i < 8; i++) { S += red[0][i]; SS += red[1][i]; }
        float mu  = S / (float)H_;
        float var = SS / (float)H_ - mu * mu;
        stats[0] = mu;
        stats[1] = rsqrtf(var + 1e-12f);
    }
    __syncthreads();
    const float mu = stats[0], rstd = stats[1];
    float* yr = y + (size_t)row * H_;
    for (int i = threadIdx.x; i < H_; i += 256) {
        float v = (xr[i] - mu) * rstd * g[i] + b[i];
        yr[i] = v;
        yp[permA(row, i)] = __uint_as_float(f2tf(v));
    }
}

// ---------------------------------------------------------------------------
// TF32 mma.sync GEMM, fragment-major operands via cp.async, 3-stage pipeline.
// CTA 128x128, 256 threads (8 warps 2Mx4N, warp tile 64x32), K-tile 32.
// No LDG/STS/cvt in the main loop.
// EPI: 0 plain row-major C; 3 QKV scatter + bias.
// ---------------------------------------------------------------------------
#define STG_FLOATS 8192                 // A 4096 + B 4096 per stage (32KB)
#define GEMM_SMEM  (3 * STG_FLOATS * 4) // 98304 B

template<int EPI>
__global__ void __launch_bounds__(256, 2) mma_gemm2(
    const float* __restrict__ Ap, const float* __restrict__ Bp,
    float* __restrict__ C,
    float* __restrict__ Cq, float* __restrict__ Ck, float* __restrict__ Cv,
    const float* __restrict__ bias, int Ntot)
{
    const int m16g0 = blockIdx.y * 8;
    const int n32g0 = blockIdx.x * 4;
    const int rowBase = blockIdx.y * 128;
    const int colBase = blockIdx.x * 128;

    extern __shared__ float smf[];
    const uint32_t smemU = (uint32_t)__cvta_generic_to_shared(smf);

    const int tx = threadIdx.x;
    const int lane = tx & 31, warp = tx >> 5;
    const int wm = (warp >> 2) * 64;
    const int wn = (warp & 3) * 32;
    const int lr = lane >> 2;
    const int lc = lane & 3;

    auto loadStage = [&](int kt, int st) {
        const uint32_t sbase = smemU + st * STG_FLOATS * 4;
        #pragma unroll
        for (int i = 0; i < 8; i++) {
            const int idx = tx + i * 256;          // float4 index 0..2047
            if (idx < 1024) {                       // A half
                const int g = idx >> 7, rem = idx & 127;
                cp16(sbase + (g * 512 + rem * 4) * 4,
                     Ap + ((size_t)(m16g0 + g) * KT_A + kt) * 512 + rem * 4);
            } else {                                // B half
                const int j = idx - 1024;
                const int nb = j >> 8, rem = j & 255;
                cp16(sbase + (4096 + nb * 1024 + rem * 4) * 4,
                     Bp + ((size_t)(n32g0 + nb) * KT_A + kt) * 1024 + rem * 4);
            }
        }
    };

    float acc[4][4][4];
    #pragma unroll
    for (int i = 0; i < 4; i++)
        #pragma unroll
        for (int j = 0; j < 4; j++)
            #pragma unroll
            for (int r = 0; r < 4; r++) acc[i][j][r] = 0.f;

    loadStage(0, 0); CP_COMMIT();
    loadStage(1, 1); CP_COMMIT();

    for (int kt = 0; kt < KT_A; kt++) {
        const int st = kt % 3;
        CP_WAIT1();
        __syncthreads();
        if (kt + 2 < KT_A) { loadStage(kt + 2, (kt + 2) % 3); CP_COMMIT(); }

        const float* sf = smf + st * STG_FLOATS;
        const float* aB = sf + (warp >> 2) * 2048;       // 4 m16-chunks
        const float* bB = sf + 4096 + (warp & 3) * 1024; // 1 n32-chunk

        #pragma unroll
        for (int ks = 0; ks < 4; ks++) {
            uint32_t af[4][4];
            #pragma unroll
            for (int mt = 0; mt < 4; mt++) {
                const float* p = aB + mt * 512 + ks * 128 + lane * 2;
                float2 x0 = *(const float2*)p;          // kh=0 -> regs 0,1
                float2 x1 = *(const float2*)(p + 64);   // kh=1 -> regs 2,3
                af[mt][0] = __float_as_uint(x0.x);
                af[mt][1] = __float_as_uint(x0.y);
                af[mt][2] = __float_as_uint(x1.x);
                af[mt][3] = __float_as_uint(x1.y);
            }
            float4 b0 = *(const float4*)(bB + ks * 256 + lane * 4);        // kh=0
            float4 b1 = *(const float4*)(bB + ks * 256 + 128 + lane * 4);  // kh=1
            uint32_t bf[4][2];
            bf[0][0] = __float_as_uint(b0.x); bf[0][1] = __float_as_uint(b1.x);
            bf[1][0] = __float_as_uint(b0.y); bf[1][1] = __float_as_uint(b1.y);
            bf[2][0] = __float_as_uint(b0.z); bf[2][1] = __float_as_uint(b1.z);
            bf[3][0] = __float_as_uint(b0.w); bf[3][1] = __float_as_uint(b1.w);
            #pragma unroll
            for (int mt = 0; mt < 4; mt++)
                #pragma unroll
                for (int nt = 0; nt < 4; nt++)
                    mma_tf32(acc[mt][nt], af[mt], bf[nt]);
        }
    }

    // ---------------- epilogue ----------------
    if (EPI == 3) {
        const int whichBlk = colBase >> 11;
        float* base = (whichBlk == 0) ? Cq : (whichBlk == 1) ? Ck : Cv;
        const int h = (colBase & 2047) >> 7;
        #pragma unroll
        for (int mt = 0; mt < 4; mt++) {
            #pragma unroll
            for (int nt = 0; nt < 4; nt++) {
                const int d  = wn + nt * 8 + 2 * lc;
                const int gn = colBase + d;
                float* a = acc[mt][nt];
                #pragma unroll
                for (int r = 0; r < 2; r++) {
                    const int m = rowBase + wm + mt * 16 + lr + r * 8;
                    const int b = m >> 11, s = m & 2047;
                    float2 o2 = make_float2(a[r * 2 + 0] + bias[gn],
                                            a[r * 2 + 1] + bias[gn + 1]);
                    *(float2*)&base[((((size_t)b * 16 + h) << 11) + s) * 128 + d] = o2;
                }
            }
        }
        return;
    }

    #pragma unroll
    for (int mt = 0; mt < 4; mt++) {
        #pragma unroll
        for (int nt = 0; nt < 4; nt++) {
            const int gm = rowBase + wm + mt * 16 + lr;
            const int gn = colBase + wn + nt * 8 + 2 * lc;
            float* a = acc[mt][nt];
            #pragma unroll
            for (int r = 0; r < 2; r++)
                *(float2*)&C[(size_t)(gm + r * 8) * Ntot + gn] =
                    make_float2(a[r * 2 + 0], a[r * 2 + 1]);
        }
    }
}

// ---------------------------------------------------------------------------
// Flash attention (math unchanged) — epilogue also writes fragment-major
// rounded ctx copy for the oproj GEMM.
// ---------------------------------------------------------------------------
#define KS_STRIDE 132
#define VS_STRIDE 136
#define K_STAGE   (64*KS_STRIDE)
#define V_STAGE   (64*VS_STRIDE)
#define P_STRIDE  68

__global__ void __launch_bounds__(256, 1) flash_kernel(
    const float* __restrict__ q, const float* __restrict__ k,
    const float* __restrict__ v, const float* __restrict__ mask,
    float* __restrict__ ctx, float* __restrict__ ctxp, float scale)
{
    const int qi = gridDim.x - 1 - blockIdx.x;
    const int rowBase = qi * 128;
    const int bh = blockIdx.y;
    const int b = bh >> 4, h = bh & 15;

    const float* Q = q + (size_t)bh * S_ * DH;
    const float* K = k + (size_t)bh * S_ * DH;
    const float* V = v + (size_t)bh * S_ * DH;
    const float* mrow = mask + (size_t)b * S_;

    extern __shared__ uint32_t smfk[];
    uint32_t* Ks = smfk;
    uint32_t* Vs = smfk + 2 * K_STAGE;
    uint32_t* Ps = Vs + 2 * V_STAGE;

    const int tx = threadIdx.x;
    const int lane = tx & 31, wid = tx >> 5;
    const int lr = lane >> 2, lc = lane & 3;

    const int r0  = wid * 16 + lr;
    const int r0g = rowBase + r0;
    const int r1g = r0g + 8;

    {
        float* qs = (float*)Ks;
        #pragma unroll
        for (int i = 0; i < 16; i++) {
            int e = tx + i * 256;
            int row = e >> 5, c4 = (e & 31) * 4;
            cp16((uint32_t)__cvta_generic_to_shared(qs + row * KS_STRIDE + c4),
                 Q + (size_t)(rowBase + row) * DH + c4);
        }
        CP_COMMIT(); CP_WAIT0();
        __syncthreads();
    }
    uint32_t qf[16][4];
    {
        const float* qs = (const float*)Ks;
        #pragma unroll
        for (int ks = 0; ks < 16; ks++) {
            qf[ks][0] = f2tf(qs[(r0)     * KS_STRIDE + ks * 8 + lc]);
            qf[ks][1] = f2tf(qs[(r0 + 8) * KS_STRIDE + ks * 8 + lc]);
            qf[ks][2] = f2tf(qs[(r0)     * KS_STRIDE + ks * 8 + lc + 4]);
            qf[ks][3] = f2tf(qs[(r0 + 8) * KS_STRIDE + ks * 8 + lc + 4]);
        }
    }
    __syncthreads();

    const int jEnd = 2 * qi + 2;

    auto cpKV = [&](int j, int st) {
        float* kd = (float*)(Ks + st * K_STAGE);
        float* vd = (float*)(Vs + st * V_STAGE);
        const float* ksrc = K + (size_t)j * 64 * DH;
        const float* vsrc = V + (size_t)j * 64 * DH;
        #pragma unroll
        for (int i = 0; i < 8; i++) {
            int e = tx + i * 256;
            int row = e >> 5, c4 = (e & 31) * 4;
            cp16((uint32_t)__cvta_generic_to_shared(kd + row * KS_STRIDE + c4),
                 ksrc + (size_t)row * DH + c4);
            cp16((uint32_t)__cvta_generic_to_shared(vd + row * VS_STRIDE + c4),
                 vsrc + (size_t)row * DH + c4);
        }
    };
    auto cvtKV = [&](int st) {
        uint32_t* kd = Ks + st * K_STAGE;
        uint32_t* vd = Vs + st * V_STAGE;
        #pragma unroll
        for (int i = 0; i < 8; i++) {
            int e = tx + i * 256;
            int row = e >> 5, c4 = (e & 31) * 4;
            float4 kf = *(float4*)(kd + row * KS_STRIDE + c4);
            uint4 ku;
            ku.x = f2tf(kf.x); ku.y = f2tf(kf.y); ku.z = f2tf(kf.z); ku.w = f2tf(kf.w);
            *(uint4*)(kd + row * KS_STRIDE + c4) = ku;
            float4 vf = *(float4*)(vd + row * VS_STRIDE + c4);
            uint4 vu;
            vu.x = f2tf(vf.x); vu.y = f2tf(vf.y); vu.z = f2tf(vf.z); vu.w = f2tf(vf.w);
            *(uint4*)(vd + row * VS_STRIDE + c4) = vu;
        }
    };

    cpKV(0, 0); CP_COMMIT(); CP_WAIT0();
    __syncthreads();
    cvtKV(0);
    __syncthreads();

    float oacc[16][4];
    #pragma unroll
    for (int i = 0; i < 16; i++)
        #pragma unroll
        for (int r = 0; r < 4; r++) oacc[i][r] = 0.f;
    float m0 = -1e30f, m1 = -1e30f, l0 = 0.f, l1 = 0.f;

    uint32_t* pw = Ps + wid * 16 * P_STRIDE;

    for (int j = 0; j < jEnd; j++) {
        const int st = j & 1;
        const bool more = (j + 1 < jEnd);
        if (more) { cpKV(j + 1, st ^ 1); CP_COMMIT(); }

        float sacc[8][4];
        #pragma unroll
        for (int nt = 0; nt < 8; nt++)
            #pragma unroll
            for (int r = 0; r < 4; r++) sacc[nt][r] = 0.f;

        const uint32_t* kbase = Ks + st * K_STAGE;
        #pragma unroll
        for (int ks = 0; ks < 16; ks++) {
            uint32_t bf[8][2];
            #pragma unroll
            for (int nt = 0; nt < 8; nt++) {
                const uint32_t* p = kbase + (nt * 8 + lr) * KS_STRIDE + ks * 8 + lc;
                bf[nt][0] = p[0];
                bf[nt][1] = p[4];
            }
            #pragma unroll
            for (int nt = 0; nt < 8; nt++)
                mma_tf32(sacc[nt], qf[ks], bf[nt]);
        }

        const int keyBase = j * 64;
        float mt0 = -1e30f, mt1 = -1e30f;
        #pragma unroll
        for (int nt = 0; nt < 8; nt++) {
            const int kcol = keyBase + nt * 8 + 2 * lc;
            float2 mk = *(const float2*)&mrow[kcol];
            float s0 = sacc[nt][0] * scale + mk.x;
            float s1 = sacc[nt][1] * scale + mk.y;
            float s2 = sacc[nt][2] * scale + mk.x;
            float s3 = sacc[nt][3] * scale + mk.y;
            if (kcol     > r0g) s0 = -10000.f;
            if (kcol + 1 > r0g) s1 = -10000.f;
            if (kcol     > r1g) s2 = -10000.f;
            if (kcol + 1 > r1g) s3 = -10000.f;
            sacc[nt][0] = s0; sacc[nt][1] = s1; sacc[nt][2] = s2; sacc[nt][3] = s3;
            mt0 = fmaxf(mt0, fmaxf(s0, s1));
            mt1 = fmaxf(mt1, fmaxf(s2, s3));
        }
        mt0 = fmaxf(mt0, __shfl_xor_sync(0xffffffffu, mt0, 1));
        mt0 = fmaxf(mt0, __shfl_xor_sync(0xffffffffu, mt0, 2));
        mt1 = fmaxf(mt1, __shfl_xor_sync(0xffffffffu, mt1, 1));
        mt1 = fmaxf(mt1, __shfl_xor_sync(0xffffffffu, mt1, 2));

        const float mn0 = fmaxf(m0, mt0), mn1 = fmaxf(m1, mt1);
        const float a0 = __expf(m0 - mn0), a1 = __expf(m1 - mn1);
        m0 = mn0; m1 = mn1;

        float ts0 = 0.f, ts1 = 0.f;
        #pragma unroll
        for (int nt = 0; nt < 8; nt++) {
            float p0 = __expf(sacc[nt][0] - mn0);
            float p1 = __expf(sacc[nt][1] - mn0);
            float p2 = __expf(sacc[nt][2] - mn1);
            float p3 = __expf(sacc[nt][3] - mn1);
            sacc[nt][0] = p0; sacc[nt][1] = p1; sacc[nt][2] = p2; sacc[nt][3] = p3;
            ts0 += p0 + p1;
            ts1 += p2 + p3;
        }
        ts0 += __shfl_xor_sync(0xffffffffu, ts0, 1);
        ts0 += __shfl_xor_sync(0xffffffffu, ts0, 2);
        ts1 += __shfl_xor_sync(0xffffffffu, ts1, 1);
        ts1 += __shfl_xor_sync(0xffffffffu, ts1, 2);
        l0 = l0 * a0 + ts0;
        l1 = l1 * a1 + ts1;

        #pragma unroll
        for (int nt = 0; nt < 16; nt++) {
            oacc[nt][0] *= a0; oacc[nt][1] *= a0;
            oacc[nt][2] *= a1; oacc[nt][3] *= a1;
        }

        __syncwarp();
        #pragma unroll
        for (int nt = 0; nt < 8; nt++) {
            uint2 u0 = make_uint2(f2tf(sacc[nt][0]), f2tf(sacc[nt][1]));
            uint2 u1 = make_uint2(f2tf(sacc[nt][2]), f2tf(sacc[nt][3]));
            *(uint2*)(pw + (lr)     * P_STRIDE + nt * 8 + 2 * lc) = u0;
            *(uint2*)(pw + (lr + 8) * P_STRIDE + nt * 8 + 2 * lc) = u1;
        }
        __syncwarp();

        const uint32_t* vbase = Vs + st * V_STAGE;
        #pragma unroll
        for (int ks = 0; ks < 8; ks++) {
            uint32_t af[4];
            af[0] = pw[(lr)     * P_STRIDE + ks * 8 + lc];
            af[1] = pw[(lr + 8) * P_STRIDE + ks * 8 + lc];
            af[2] = pw[(lr)     * P_STRIDE + ks * 8 + lc + 4];
            af[3] = pw[(lr + 8) * P_STRIDE + ks * 8 + lc + 4];
            #pragma unroll
            for (int nt = 0; nt < 16; nt++) {
                const uint32_t* p = vbase + (ks * 8 + lc) * VS_STRIDE + nt * 8 + lr;
                uint32_t bf2[2] = { p[0], p[4 * VS_STRIDE] };
                mma_tf32(oacc[nt], af, bf2);
            }
        }

        if (more) {
            CP_WAIT0();
            __syncthreads();
            cvtKV(st ^ 1);
            __syncthreads();
        }
    }

    // epilogue: exact ctx [B,S,H] + fragment-major rounded copy
    const float inv0 = 1.0f / l0;
    const float inv1 = 1.0f / l1;
    const size_t o0 = ((size_t)b * S_ + r0g) * H_ + h * 128 + 2 * lc;
    const size_t o1 = ((size_t)b * S_ + r1g) * H_ + h * 128 + 2 * lc;
    #pragma unroll
    for (int nt = 0; nt < 16; nt++) {
        float v0 = oacc[nt][0] * inv0, v1 = oacc[nt][1] * inv0;
        float v2 = oacc[nt][2] * inv1, v3 = oacc[nt][3] * inv1;
        *(float2*)(ctx + o0 + nt * 8) = make_float2(v0, v1);
        *(float2*)(ctx + o1 + nt * 8) = make_float2(v2, v3);
        // perm copy: element pairs (row r0g=rh0, row r1g=rh1) are contiguous
        const int mrow_b = b * S_ + 0;   // permA uses global m over 4096 rows
        const int mg = mrow_b + r0g;     // m = b*2048 + r0g
        const int k0 = h * 128 + nt * 8 + 2 * lc;
        *(float2*)(ctxp + permA(mg, k0)) =
            make_float2(__uint_as_float(f2tf(v0)), __uint_as_float(f2tf(v2)));
        *(float2*)(ctxp + permA(mg, k0 + 1)) =
            make_float2(__uint_as_float(f2tf(v1)), __uint_as_float(f2tf(v3)));
    }
}

// ---------------------------------------------------------------------------
// kernel_launch
// ---------------------------------------------------------------------------
extern "C" void kernel_launch(void* const* d_in, const int* in_sizes, int n_in,
                              void* d_out, int out_size)
{
    const float* x    = (const float*)d_in[0];
    const float* mask = (const float*)d_in[1];
    const float* qkvw = (const float*)d_in[2];
    const float* qkvb = (const float*)d_in[3];
    const float* ow   = (const float*)d_in[4];
    const float* nw   = (const float*)d_in[5];
    const float* nb   = (const float*)d_in[6];

    float* out     = (float*)d_out;
    float* out_o   = out;
    float* out_k   = out + 1 * BSH;
    float* out_v   = out + 2 * BSH;
    float* out_ctx = out + 3 * BSH;
    float* out_ln  = out + 4 * BSH;

    float *q, *lnp, *ctxp, *qkvwP, *owP;
    cudaGetSymbolAddress((void**)&q,     g_q);
    cudaGetSymbolAddress((void**)&lnp,   g_lnp);
    cudaGetSymbolAddress((void**)&ctxp,  g_ctxp);
    cudaGetSymbolAddress((void**)&qkvwP, g_qkvwP);
    cudaGetSymbolAddress((void**)&owP,   g_owP);

    const int FLASH_SMEM = (2 * K_STAGE + 2 * V_STAGE + 8 * 16 * P_STRIDE) * 4;

    cudaFuncSetAttribute(mma_gemm2<3>, cudaFuncAttributeMaxDynamicSharedMemorySize, GEMM_SMEM);
    cudaFuncSetAttribute(mma_gemm2<0>, cudaFuncAttributeMaxDynamicSharedMemorySize, GEMM_SMEM);
    cudaFuncSetAttribute(flash_kernel, cudaFuncAttributeMaxDynamicSharedMemorySize, FLASH_SMEM);

    const float scale = 1.0f / sqrtf((float)DH);

    // 0. Weight prep (fragment-major, tf32-rounded)
    prep_b<<<dim3(KT_A, 3 * H_ / 32), 256>>>(qkvw, qkvwP, 3 * H_);
    prep_b<<<dim3(KT_A, H_ / 32), 256>>>(ow, owP, H_);

    // 1. LayerNorm -> out_ln + lnp (fragment-major rounded)
    ln_kernel<<<B_ * S_, 256>>>(x, nw, nb, out_ln, lnp);

    // 2. QKV GEMM + bias, scatter q/k/v in [B,H,S,dh]
    mma_gemm2<3><<<dim3(48, 32), 256, GEMM_SMEM>>>(
        lnp, qkvwP, nullptr, q, out_k, out_v, qkvb, 3 * H_);

    // 3. Flash attention -> out_ctx + ctxp
    flash_kernel<<<dim3(16, BH), 256, FLASH_SMEM>>>(
        q, out_k, out_v, mask, out_ctx, ctxp, scale);

    // 4. Output projection
    mma_gemm2<0><<<dim3(16, 32), 256, GEMM_SMEM>>>(
        ctxp, owP, out_o, nullptr, nullptr, nullptr, nullptr, H_);
}